// round 1
// baseline (speedup 1.0000x reference)
#include <cuda_runtime.h>
#include <math.h>

#define BB    8192
#define D_IN  512
#define H1    4096
#define CH    256
#define HR    1024
#define H2    4096
#define D_OUTN 512

// ---------------- scratch (device globals; no allocation allowed) ----------
__device__ float g_a  [(size_t)BB * H1];   // 128 MB
__device__ float g_s  [(size_t)BB * CH];
__device__ float g_xr [(size_t)BB * CH];
__device__ float g_g1 [(size_t)BB * HR];
__device__ float g_g2 [(size_t)BB * HR];
__device__ float g_xr2[(size_t)BB * CH];
__device__ float g_t  [(size_t)BB * H2];   // 128 MB

// ---------------- GEMM: C[M,N] = act(A[M,K] * W[N,K]^T + bias) -------------
// Both operands K-contiguous (weights are [N,K] row-major). 128x128 tile,
// 256 threads, 8x8 per thread, K-tile 16, float4 global loads.
// ACT: 0 = none, 1 = relu, 2 = tanh
template <int ACT>
__global__ void __launch_bounds__(256, 2)
gemm_nt(const float* __restrict__ A, const float* __restrict__ W,
        const float* __restrict__ bias, float* __restrict__ C,
        int M, int N, int K)
{
    __shared__ float As[16][132];
    __shared__ float Ws[16][132];

    const int bm = blockIdx.y * 128;
    const int bn = blockIdx.x * 128;
    const int tid = threadIdx.x;
    const int tx = tid & 15;          // 0..15 -> N sub-tile
    const int ty = tid >> 4;          // 0..15 -> M sub-tile

    // global-load mapping: each thread loads 2 float4 per operand tile
    const int lr = tid >> 2;          // 0..63 (row within first half)
    const int lc = (tid & 3) * 4;     // 0,4,8,12

    float acc[8][8];
#pragma unroll
    for (int i = 0; i < 8; i++)
#pragma unroll
        for (int j = 0; j < 8; j++) acc[i][j] = 0.0f;

    const float* Ap0 = A + (size_t)(bm + lr)      * K + lc;
    const float* Ap1 = A + (size_t)(bm + lr + 64) * K + lc;
    const float* Wp0 = W + (size_t)(bn + lr)      * K + lc;
    const float* Wp1 = W + (size_t)(bn + lr + 64) * K + lc;

    for (int k0 = 0; k0 < K; k0 += 16) {
        float4 a0 = *(const float4*)(Ap0 + k0);
        float4 a1 = *(const float4*)(Ap1 + k0);
        float4 w0 = *(const float4*)(Wp0 + k0);
        float4 w1 = *(const float4*)(Wp1 + k0);

        __syncthreads();   // previous compute done before overwrite
        As[lc + 0][lr]      = a0.x; As[lc + 1][lr]      = a0.y;
        As[lc + 2][lr]      = a0.z; As[lc + 3][lr]      = a0.w;
        As[lc + 0][lr + 64] = a1.x; As[lc + 1][lr + 64] = a1.y;
        As[lc + 2][lr + 64] = a1.z; As[lc + 3][lr + 64] = a1.w;
        Ws[lc + 0][lr]      = w0.x; Ws[lc + 1][lr]      = w0.y;
        Ws[lc + 2][lr]      = w0.z; Ws[lc + 3][lr]      = w0.w;
        Ws[lc + 0][lr + 64] = w1.x; Ws[lc + 1][lr + 64] = w1.y;
        Ws[lc + 2][lr + 64] = w1.z; Ws[lc + 3][lr + 64] = w1.w;
        __syncthreads();

#pragma unroll
        for (int kk = 0; kk < 16; kk++) {
            float4 af0 = *(const float4*)&As[kk][ty * 8];
            float4 af1 = *(const float4*)&As[kk][ty * 8 + 4];
            float4 bf0 = *(const float4*)&Ws[kk][tx * 8];
            float4 bf1 = *(const float4*)&Ws[kk][tx * 8 + 4];
            float av[8] = {af0.x, af0.y, af0.z, af0.w, af1.x, af1.y, af1.z, af1.w};
            float bv[8] = {bf0.x, bf0.y, bf0.z, bf0.w, bf1.x, bf1.y, bf1.z, bf1.w};
#pragma unroll
            for (int i = 0; i < 8; i++)
#pragma unroll
                for (int j = 0; j < 8; j++)
                    acc[i][j] = fmaf(av[i], bv[j], acc[i][j]);
        }
    }

    // epilogue: bias + activation, vectorized stores
    float4 bz0 = *(const float4*)(bias + bn + tx * 8);
    float4 bz1 = *(const float4*)(bias + bn + tx * 8 + 4);
    float bb[8] = {bz0.x, bz0.y, bz0.z, bz0.w, bz1.x, bz1.y, bz1.z, bz1.w};

#pragma unroll
    for (int i = 0; i < 8; i++) {
        int row = bm + ty * 8 + i;
        float o[8];
#pragma unroll
        for (int j = 0; j < 8; j++) {
            float v = acc[i][j] + bb[j];
            if (ACT == 1) v = fmaxf(v, 0.0f);
            if (ACT == 2) v = tanhf(v);
            o[j] = v;
        }
        float* cp = C + (size_t)row * N + bn + tx * 8;
        *(float4*)(cp)     = make_float4(o[0], o[1], o[2], o[3]);
        *(float4*)(cp + 4) = make_float4(o[4], o[5], o[6], o[7]);
    }
}

// ---------------- per-row channel: norm -> fade+noise -> LS -> ZF ----------
__device__ __forceinline__ float blockReduce128(float v, volatile float* sm)
{
#pragma unroll
    for (int o = 16; o; o >>= 1) v += __shfl_down_sync(0xffffffffu, v, o);
    int lane = threadIdx.x & 31, warp = threadIdx.x >> 5;
    __syncthreads();               // protect sm reuse from previous reduce
    if (lane == 0) sm[warp] = v;
    __syncthreads();
    return sm[0] + sm[1] + sm[2] + sm[3];
}

__global__ void channel_kernel(const float* __restrict__ s,
                               const float* __restrict__ noise,
                               const float* __restrict__ h,
                               float* __restrict__ xr)
{
    __shared__ float sm[4];
    const int row = blockIdx.x;
    const int t = threadIdx.x;     // one complex pair per thread (128 pairs)

    float2 sp = *(const float2*)(s + (size_t)row * CH + 2 * t);
    float sumsq = blockReduce128(sp.x * sp.x + sp.y * sp.y, sm);
    float scale = sqrtf(128.0f) * rsqrtf(sumsq);   // sqrt(2n * 0.5)/||s||
    float txr = scale * sp.x, txi = scale * sp.y;

    float h0 = h[0], h1 = h[1];
    float2 np = *(const float2*)(noise + (size_t)row * CH + 2 * t);
    float yr = h0 * txr - h1 * txi + np.x;
    float yi = h0 * txi + h1 * txr + np.y;

    float numr = blockReduce128(yr * txr + yi * txi, sm);
    float numi = blockReduce128(yi * txr - yr * txi, sm);
    float den  = blockReduce128(txr * txr + txi * txi, sm);

    float hr = numr / den, hi = numi / den;
    float d2 = hr * hr + hi * hi + 1e-12f;
    float xe_r = (yr * hr + yi * hi) / d2;
    float xe_i = (yi * hr - yr * hi) / d2;
    *(float2*)(xr + (size_t)row * CH + 2 * t) = make_float2(xe_r, xe_i);
}

// ---------------- RTN tail: h_inv = g2 @ w_rtn3^T + b; 3-tap complex conv --
__global__ void __launch_bounds__(256)
rtn_tail(const float* __restrict__ g2, const float* __restrict__ w_rtn3,
         const float* __restrict__ b_rtn3, const float* __restrict__ xr,
         float* __restrict__ xr2)
{
    __shared__ float gs[HR];
    __shared__ float xs[CH];
    __shared__ float red[6][8];
    __shared__ float hinv[6];

    const int row = blockIdx.x, tid = threadIdx.x;
    for (int i = tid; i < HR; i += 256) gs[i] = g2[(size_t)row * HR + i];
    for (int i = tid; i < CH; i += 256) xs[i] = xr[(size_t)row * CH + i];
    __syncthreads();

    float acc[6] = {0, 0, 0, 0, 0, 0};
    for (int i = tid; i < HR; i += 256) {
        float gv = gs[i];
#pragma unroll
        for (int o = 0; o < 6; o++) acc[o] += gv * w_rtn3[o * HR + i];
    }
#pragma unroll
    for (int o = 0; o < 6; o++) {
        float v = acc[o];
#pragma unroll
        for (int sft = 16; sft; sft >>= 1) v += __shfl_down_sync(0xffffffffu, v, sft);
        if ((tid & 31) == 0) red[o][tid >> 5] = v;
    }
    __syncthreads();
    if (tid < 6) {
        float v = 0;
#pragma unroll
        for (int w = 0; w < 8; w++) v += red[tid][w];
        hinv[tid] = v + b_rtn3[tid];
    }
    __syncthreads();

    if (tid < 128) {
        float or_ = 0.0f, oi_ = 0.0f;
#pragma unroll
        for (int l = 0; l < 3; l++) {
            if (tid - l >= 0) {
                float hrr = hinv[2 * l], hii = hinv[2 * l + 1];
                float xrr = xs[2 * (tid - l)], xii = xs[2 * (tid - l) + 1];
                or_ += hrr * xrr - hii * xii;
                oi_ += hrr * xii + hii * xrr;
            }
        }
        *(float2*)(xr2 + (size_t)row * CH + 2 * tid) = make_float2(or_, oi_);
    }
}

// ---------------- launcher --------------------------------------------------
extern "C" void kernel_launch(void* const* d_in, const int* in_sizes, int n_in,
                              void* d_out, int out_size)
{
    const float* x     = (const float*)d_in[0];
    const float* w1    = (const float*)d_in[1];
    const float* b1    = (const float*)d_in[2];
    const float* w2    = (const float*)d_in[3];
    const float* b2    = (const float*)d_in[4];
    const float* wr1   = (const float*)d_in[5];
    const float* br1   = (const float*)d_in[6];
    const float* wr2   = (const float*)d_in[7];
    const float* br2   = (const float*)d_in[8];
    const float* wr3   = (const float*)d_in[9];
    const float* br3   = (const float*)d_in[10];
    const float* w3    = (const float*)d_in[11];
    const float* b3    = (const float*)d_in[12];
    const float* w4    = (const float*)d_in[13];
    const float* b4    = (const float*)d_in[14];
    const float* h     = (const float*)d_in[15];
    const float* noise = (const float*)d_in[16];

    float *a, *s, *xr, *g1, *g2, *xr2, *t;
    cudaGetSymbolAddress((void**)&a,   g_a);
    cudaGetSymbolAddress((void**)&s,   g_s);
    cudaGetSymbolAddress((void**)&xr,  g_xr);
    cudaGetSymbolAddress((void**)&g1,  g_g1);
    cudaGetSymbolAddress((void**)&g2,  g_g2);
    cudaGetSymbolAddress((void**)&xr2, g_xr2);
    cudaGetSymbolAddress((void**)&t,   g_t);

    // encoder
    gemm_nt<1><<<dim3(H1 / 128, BB / 128), 256>>>(x,  w1, b1, a, BB, H1, D_IN);
    gemm_nt<0><<<dim3(CH / 128, BB / 128), 256>>>(a,  w2, b2, s, BB, CH, H1);
    // channel + equalization (per-row)
    channel_kernel<<<BB, 128>>>(s, noise, h, xr);
    // RTN
    gemm_nt<2><<<dim3(HR / 128, BB / 128), 256>>>(xr, wr1, br1, g1, BB, HR, CH);
    gemm_nt<2><<<dim3(HR / 128, BB / 128), 256>>>(g1, wr2, br2, g2, BB, HR, HR);
    rtn_tail<<<BB, 256>>>(g2, wr3, br3, xr, xr2);
    // decoder
    gemm_nt<1><<<dim3(H2 / 128, BB / 128), 256>>>(xr2, w3, b3, t, BB, H2, CH);
    gemm_nt<0><<<dim3(D_OUTN / 128, BB / 128), 256>>>(t, w4, b4, (float*)d_out,
                                                      BB, D_OUTN, H2);
}

// round 3
// speedup vs baseline: 2.2760x; 2.2760x over previous
#include <cuda_runtime.h>
#include <cstdint>
#include <math.h>

#define BB    8192
#define D_IN  512
#define H1    4096
#define CH    256
#define HR    1024
#define H2    4096
#define D_OUTN 512

// ---------------- scratch (device globals; no allocation allowed) ----------
__device__ float g_a  [(size_t)BB * H1];
__device__ float g_s  [(size_t)BB * CH];
__device__ float g_xr [(size_t)BB * CH];
__device__ float g_g1 [(size_t)BB * HR];
__device__ float g_g2 [(size_t)BB * HR];
__device__ float g_xr2[(size_t)BB * CH];
__device__ float g_t  [(size_t)BB * H2];
__device__ float g_xt [(size_t)BB * D_IN];               // tf32-rounded x
__device__ float g_wq [(size_t)7602176];                  // tf32-rounded weights

#define OFF_W1  0
#define OFF_W2  2097152
#define OFF_WR1 3145728
#define OFF_WR2 3407872
#define OFF_W3  4456448
#define OFF_W4  5505024

// ---------------- helpers ----------------------------------------------------
__device__ __forceinline__ float rtf32(float x) {
    uint32_t u;
    asm("cvt.rna.tf32.f32 %0, %1;" : "=r"(u) : "f"(x));
    return __uint_as_float(u);
}

__device__ __forceinline__ uint32_t smem_u32(const void* p) {
    uint32_t a;
    asm("{ .reg .u64 t; cvta.to.shared.u64 t, %1; cvt.u32.u64 %0, t; }"
        : "=r"(a) : "l"(p));
    return a;
}

__device__ __forceinline__ void cp_async16(uint32_t dst, const void* src) {
    asm volatile("cp.async.cg.shared.global [%0], [%1], 16;"
        :: "r"(dst), "l"(src) : "memory");
}
__device__ __forceinline__ void cp_commit() {
    asm volatile("cp.async.commit_group;" ::: "memory");
}
template <int N>
__device__ __forceinline__ void cp_wait() {
    asm volatile("cp.async.wait_group %0;" :: "n"(N) : "memory");
}

__device__ __forceinline__ void mma_tf32(float* d, const uint32_t* a,
                                         uint32_t b0, uint32_t b1) {
    asm volatile(
        "mma.sync.aligned.m16n8k8.row.col.f32.tf32.tf32.f32 "
        "{%0,%1,%2,%3}, {%4,%5,%6,%7}, {%8,%9}, {%0,%1,%2,%3};"
        : "+f"(d[0]), "+f"(d[1]), "+f"(d[2]), "+f"(d[3])
        : "r"(a[0]), "r"(a[1]), "r"(a[2]), "r"(a[3]), "r"(b0), "r"(b1));
}

// ---------------- elementwise tf32 rounding pass ----------------------------
__global__ void round_tf32_kernel(const float* __restrict__ src,
                                  float* __restrict__ dst, int n4) {
    int i = blockIdx.x * blockDim.x + threadIdx.x;
    int stride = gridDim.x * blockDim.x;
    for (; i < n4; i += stride) {
        float4 v = ((const float4*)src)[i];
        v.x = rtf32(v.x); v.y = rtf32(v.y); v.z = rtf32(v.z); v.w = rtf32(v.w);
        ((float4*)dst)[i] = v;
    }
}

// ---------------- tf32 mma.sync GEMM -----------------------------------------
// C[M,N] = act(A[M,K] @ W[N,K]^T + bias). Tile 128x128x32, cp.async double buf.
// 256 threads, warp grid 4(M) x 2(N), warp tile 32x64, atoms m16n8k8.
#define BM 128
#define BN 128
#define BK 32
#define ROWF 36                       // padded row length in floats (bank-safe)
#define ATILE_F (128 * ROWF)          // 4608 floats per operand tile
#define BUF_F   (2 * ATILE_F)         // 9216 floats per buffer (A + B)
#define SMEM_TOTAL (2 * BUF_F * 4)    // 73728 bytes

template <int ACT, int ROUND>   // ACT: 0 none, 1 relu, 2 tanh
__global__ void __launch_bounds__(256)
gemm_tc(const float* __restrict__ A, const float* __restrict__ W,
        const float* __restrict__ bias, float* __restrict__ C,
        int M, int N, int K)
{
    extern __shared__ float smf[];
    const uint32_t sb = smem_u32(smf);
    const int tid  = threadIdx.x;
    const int wid  = tid >> 5, lane = tid & 31;
    const int g    = lane >> 2, c = lane & 3;       // mma group / thread-in-group
    const int wm   = wid & 3, wn = wid >> 2;        // warp grid 4x2
    const int bm   = blockIdx.x * BM;
    const int bn   = blockIdx.y * BN;

    // loader mapping: thread -> row (0..127), k-quarter (0 or 16)
    const int lrow = tid >> 1;
    const int lk   = (tid & 1) * 16;
    const float* Ag = A + (size_t)(bm + lrow) * K + lk;
    const float* Bg = W + (size_t)(bn + lrow) * K + lk;
    const uint32_t stA = sb + (uint32_t)(lrow * ROWF + lk) * 4;
    const uint32_t stB = stA + ATILE_F * 4;

    float acc[2][8][4];
#pragma unroll
    for (int mt = 0; mt < 2; mt++)
#pragma unroll
        for (int nt = 0; nt < 8; nt++)
#pragma unroll
            for (int r = 0; r < 4; r++) acc[mt][nt][r] = 0.0f;

    const int nk = K / BK;

    // prefetch tile 0 -> buffer 0
#pragma unroll
    for (int i = 0; i < 4; i++) {
        cp_async16(stA + i * 16, Ag + i * 4);
        cp_async16(stB + i * 16, Bg + i * 4);
    }
    cp_commit();

    // fragment base offsets (floats)
    const int aoff = (wm * 32 + g) * ROWF + c;
    const int boff = ATILE_F + (wn * 64 + g) * ROWF + c;

    for (int it = 0; it < nk; ++it) {
        const int buf = it & 1;
        if (it + 1 < nk) {
            const uint32_t d = (uint32_t)(((it + 1) & 1) * BUF_F) * 4;
            const float* Ap = Ag + (size_t)(it + 1) * BK;
            const float* Bp = Bg + (size_t)(it + 1) * BK;
#pragma unroll
            for (int i = 0; i < 4; i++) {
                cp_async16(stA + d + i * 16, Ap + i * 4);
                cp_async16(stB + d + i * 16, Bp + i * 4);
            }
            cp_commit();
            cp_wait<1>();
        } else {
            cp_wait<0>();
        }
        __syncthreads();

        const int base = buf * BUF_F;
#pragma unroll
        for (int ks = 0; ks < 4; ++ks) {
            uint32_t a[2][4];
#pragma unroll
            for (int mt = 0; mt < 2; ++mt) {
                const int ab = base + aoff + mt * 16 * ROWF + ks * 8;
                a[mt][0] = __float_as_uint(smf[ab]);
                a[mt][1] = __float_as_uint(smf[ab + 8 * ROWF]);
                a[mt][2] = __float_as_uint(smf[ab + 4]);
                a[mt][3] = __float_as_uint(smf[ab + 8 * ROWF + 4]);
            }
#pragma unroll
            for (int nt = 0; nt < 8; ++nt) {
                const int bbp = base + boff + nt * 8 * ROWF + ks * 8;
                uint32_t b0 = __float_as_uint(smf[bbp]);
                uint32_t b1 = __float_as_uint(smf[bbp + 4]);
                mma_tf32(acc[0][nt], a[0], b0, b1);
                mma_tf32(acc[1][nt], a[1], b0, b1);
            }
        }
        __syncthreads();
    }

    // epilogue: bias + activation (+ tf32 round), float2 stores
#pragma unroll
    for (int nt = 0; nt < 8; ++nt) {
        const int colb = bn + wn * 64 + nt * 8 + 2 * c;
        const float bz0 = bias[colb], bz1 = bias[colb + 1];
#pragma unroll
        for (int mt = 0; mt < 2; ++mt) {
            const int row0 = bm + wm * 32 + mt * 16 + g;
            float o0 = acc[mt][nt][0] + bz0;
            float o1 = acc[mt][nt][1] + bz1;
            float o2 = acc[mt][nt][2] + bz0;
            float o3 = acc[mt][nt][3] + bz1;
            if (ACT == 1) {
                o0 = fmaxf(o0, 0.f); o1 = fmaxf(o1, 0.f);
                o2 = fmaxf(o2, 0.f); o3 = fmaxf(o3, 0.f);
            }
            if (ACT == 2) {
                o0 = tanhf(o0); o1 = tanhf(o1);
                o2 = tanhf(o2); o3 = tanhf(o3);
            }
            if (ROUND) {
                o0 = rtf32(o0); o1 = rtf32(o1);
                o2 = rtf32(o2); o3 = rtf32(o3);
            }
            *(float2*)(C + (size_t)row0 * N + colb)       = make_float2(o0, o1);
            *(float2*)(C + (size_t)(row0 + 8) * N + colb) = make_float2(o2, o3);
        }
    }
}

// ---------------- per-row channel: norm -> fade+noise -> LS -> ZF ----------
__device__ __forceinline__ float blockReduce128(float v, volatile float* sm)
{
#pragma unroll
    for (int o = 16; o; o >>= 1) v += __shfl_down_sync(0xffffffffu, v, o);
    int lane = threadIdx.x & 31, warp = threadIdx.x >> 5;
    __syncthreads();
    if (lane == 0) sm[warp] = v;
    __syncthreads();
    return sm[0] + sm[1] + sm[2] + sm[3];
}

__global__ void channel_kernel(const float* __restrict__ s,
                               const float* __restrict__ noise,
                               const float* __restrict__ h,
                               float* __restrict__ xr)
{
    __shared__ float sm[4];
    const int row = blockIdx.x;
    const int t = threadIdx.x;

    float2 sp = *(const float2*)(s + (size_t)row * CH + 2 * t);
    float sumsq = blockReduce128(sp.x * sp.x + sp.y * sp.y, sm);
    float scale = sqrtf(128.0f) * rsqrtf(sumsq);
    float txr = scale * sp.x, txi = scale * sp.y;

    float h0 = h[0], h1 = h[1];
    float2 np = *(const float2*)(noise + (size_t)row * CH + 2 * t);
    float yr = h0 * txr - h1 * txi + np.x;
    float yi = h0 * txi + h1 * txr + np.y;

    float numr = blockReduce128(yr * txr + yi * txi, sm);
    float numi = blockReduce128(yi * txr - yr * txi, sm);
    float den  = blockReduce128(txr * txr + txi * txi, sm);

    float hr = numr / den, hi = numi / den;
    float d2 = hr * hr + hi * hi + 1e-12f;
    float xe_r = (yr * hr + yi * hi) / d2;
    float xe_i = (yi * hr - yr * hi) / d2;
    // round for the downstream tf32 GEMM
    *(float2*)(xr + (size_t)row * CH + 2 * t) = make_float2(rtf32(xe_r), rtf32(xe_i));
}

// ---------------- RTN tail: h_inv = g2 @ w_rtn3^T + b; 3-tap complex conv --
__global__ void __launch_bounds__(256)
rtn_tail(const float* __restrict__ g2, const float* __restrict__ w_rtn3,
         const float* __restrict__ b_rtn3, const float* __restrict__ xr,
         float* __restrict__ xr2)
{
    __shared__ float gs[HR];
    __shared__ float xs[CH];
    __shared__ float red[6][8];
    __shared__ float hinv[6];

    const int row = blockIdx.x, tid = threadIdx.x;
    for (int i = tid; i < HR; i += 256) gs[i] = g2[(size_t)row * HR + i];
    for (int i = tid; i < CH; i += 256) xs[i] = xr[(size_t)row * CH + i];
    __syncthreads();

    float acc[6] = {0, 0, 0, 0, 0, 0};
    for (int i = tid; i < HR; i += 256) {
        float gv = gs[i];
#pragma unroll
        for (int o = 0; o < 6; o++) acc[o] += gv * w_rtn3[o * HR + i];
    }
#pragma unroll
    for (int o = 0; o < 6; o++) {
        float v = acc[o];
#pragma unroll
        for (int sft = 16; sft; sft >>= 1) v += __shfl_down_sync(0xffffffffu, v, sft);
        if ((tid & 31) == 0) red[o][tid >> 5] = v;
    }
    __syncthreads();
    if (tid < 6) {
        float v = 0;
#pragma unroll
        for (int w = 0; w < 8; w++) v += red[tid][w];
        hinv[tid] = v + b_rtn3[tid];
    }
    __syncthreads();

    if (tid < 128) {
        float or_ = 0.0f, oi_ = 0.0f;
#pragma unroll
        for (int l = 0; l < 3; l++) {
            if (tid - l >= 0) {
                float hrr = hinv[2 * l], hii = hinv[2 * l + 1];
                float xrr = xs[2 * (tid - l)], xii = xs[2 * (tid - l) + 1];
                or_ += hrr * xrr - hii * xii;
                oi_ += hrr * xii + hii * xrr;
            }
        }
        *(float2*)(xr2 + (size_t)row * CH + 2 * tid) =
            make_float2(rtf32(or_), rtf32(oi_));
    }
}

// ---------------- launcher --------------------------------------------------
extern "C" void kernel_launch(void* const* d_in, const int* in_sizes, int n_in,
                              void* d_out, int out_size)
{
    const float* x     = (const float*)d_in[0];
    const float* w1    = (const float*)d_in[1];
    const float* b1    = (const float*)d_in[2];
    const float* w2    = (const float*)d_in[3];
    const float* b2    = (const float*)d_in[4];
    const float* wr1   = (const float*)d_in[5];
    const float* br1   = (const float*)d_in[6];
    const float* wr2   = (const float*)d_in[7];
    const float* br2   = (const float*)d_in[8];
    const float* wr3   = (const float*)d_in[9];
    const float* br3   = (const float*)d_in[10];
    const float* w3    = (const float*)d_in[11];
    const float* b3    = (const float*)d_in[12];
    const float* w4    = (const float*)d_in[13];
    const float* b4    = (const float*)d_in[14];
    const float* h     = (const float*)d_in[15];
    const float* noise = (const float*)d_in[16];

    float *a, *s, *xr, *g1, *g2, *xr2, *t, *xt, *wq;
    cudaGetSymbolAddress((void**)&a,   g_a);
    cudaGetSymbolAddress((void**)&s,   g_s);
    cudaGetSymbolAddress((void**)&xr,  g_xr);
    cudaGetSymbolAddress((void**)&g1,  g_g1);
    cudaGetSymbolAddress((void**)&g2,  g_g2);
    cudaGetSymbolAddress((void**)&xr2, g_xr2);
    cudaGetSymbolAddress((void**)&t,   g_t);
    cudaGetSymbolAddress((void**)&xt,  g_xt);
    cudaGetSymbolAddress((void**)&wq,  g_wq);

    cudaFuncSetAttribute(gemm_tc<1, 1>, cudaFuncAttributeMaxDynamicSharedMemorySize, SMEM_TOTAL);
    cudaFuncSetAttribute(gemm_tc<0, 0>, cudaFuncAttributeMaxDynamicSharedMemorySize, SMEM_TOTAL);
    cudaFuncSetAttribute(gemm_tc<2, 1>, cudaFuncAttributeMaxDynamicSharedMemorySize, SMEM_TOTAL);
    cudaFuncSetAttribute(gemm_tc<2, 0>, cudaFuncAttributeMaxDynamicSharedMemorySize, SMEM_TOTAL);

    // pre-round inputs + weights to nearest-tf32 (HW truncates; RN is unbiased)
    round_tf32_kernel<<<1024, 256>>>(x,   xt,            BB * D_IN / 4);
    round_tf32_kernel<<<1024, 256>>>(w1,  wq + OFF_W1,   H1 * D_IN / 4);
    round_tf32_kernel<<<1024, 256>>>(w2,  wq + OFF_W2,   CH * H1 / 4);
    round_tf32_kernel<<<256,  256>>>(wr1, wq + OFF_WR1,  HR * CH / 4);
    round_tf32_kernel<<<1024, 256>>>(wr2, wq + OFF_WR2,  HR * HR / 4);
    round_tf32_kernel<<<1024, 256>>>(w3,  wq + OFF_W3,   H2 * CH / 4);
    round_tf32_kernel<<<1024, 256>>>(w4,  wq + OFF_W4,   D_OUTN * H2 / 4);

    // encoder
    gemm_tc<1, 1><<<dim3(BB / BM, H1 / BN), 256, SMEM_TOTAL>>>(
        xt, wq + OFF_W1, b1, a, BB, H1, D_IN);
    gemm_tc<0, 0><<<dim3(BB / BM, CH / BN), 256, SMEM_TOTAL>>>(
        a, wq + OFF_W2, b2, s, BB, CH, H1);
    // channel + equalization
    channel_kernel<<<BB, 128>>>(s, noise, h, xr);
    // RTN
    gemm_tc<2, 1><<<dim3(BB / BM, HR / BN), 256, SMEM_TOTAL>>>(
        xr, wq + OFF_WR1, br1, g1, BB, HR, CH);
    gemm_tc<2, 0><<<dim3(BB / BM, HR / BN), 256, SMEM_TOTAL>>>(
        g1, wq + OFF_WR2, br2, g2, BB, HR, HR);
    rtn_tail<<<BB, 256>>>(g2, wr3, br3, xr, xr2);
    // decoder
    gemm_tc<1, 1><<<dim3(BB / BM, H2 / BN), 256, SMEM_TOTAL>>>(
        xr2, wq + OFF_W3, b3, t, BB, H2, CH);
    gemm_tc<0, 0><<<dim3(BB / BM, D_OUTN / BN), 256, SMEM_TOTAL>>>(
        t, wq + OFF_W4, b4, (float*)d_out, BB, D_OUTN, H2);
}

// round 4
// speedup vs baseline: 4.3220x; 1.8990x over previous
#include <cuda_runtime.h>
#include <cuda_fp16.h>
#include <cstdint>
#include <math.h>

#define BB    8192
#define D_IN  512
#define H1    4096
#define CH    256
#define HR    1024
#define H2    4096
#define D_OUTN 512

// ---------------- scratch (device globals; no allocation allowed) ----------
__device__ __half g_xh [(size_t)BB * D_IN];
__device__ __half g_wh [(size_t)7602176];       // all weights, fp16
__device__ __half g_ah [(size_t)BB * H1];
__device__ __half g_sh [(size_t)BB * CH];
__device__ __half g_xrh[(size_t)BB * CH];
__device__ __half g_g1h[(size_t)BB * HR];
__device__ __half g_g2h[(size_t)BB * HR];
__device__ __half g_x2h[(size_t)BB * CH];
__device__ __half g_th [(size_t)BB * H2];

#define OFF_W1  0
#define OFF_W2  2097152
#define OFF_WR1 3145728
#define OFF_WR2 3407872
#define OFF_W3  4456448
#define OFF_W4  5505024

// ---------------- helpers ----------------------------------------------------
__device__ __forceinline__ uint32_t smem_u32(const void* p) {
    uint32_t a;
    asm("{ .reg .u64 t; cvta.to.shared.u64 t, %1; cvt.u32.u64 %0, t; }"
        : "=r"(a) : "l"(p));
    return a;
}

__device__ __forceinline__ void cp_async16(uint32_t dst, const void* src) {
    asm volatile("cp.async.cg.shared.global [%0], [%1], 16;"
        :: "r"(dst), "l"(src) : "memory");
}
__device__ __forceinline__ void cp_commit() {
    asm volatile("cp.async.commit_group;" ::: "memory");
}
template <int N>
__device__ __forceinline__ void cp_wait() {
    asm volatile("cp.async.wait_group %0;" :: "n"(N) : "memory");
}

__device__ __forceinline__ void ldsm4(uint32_t& r0, uint32_t& r1,
                                      uint32_t& r2, uint32_t& r3, uint32_t a) {
    asm volatile("ldmatrix.sync.aligned.m8n8.x4.shared.b16 {%0,%1,%2,%3}, [%4];"
        : "=r"(r0), "=r"(r1), "=r"(r2), "=r"(r3) : "r"(a));
}

__device__ __forceinline__ void mma_f16(float* d, const uint32_t* a,
                                        uint32_t b0, uint32_t b1) {
    asm volatile(
        "mma.sync.aligned.m16n8k16.row.col.f32.f16.f16.f32 "
        "{%0,%1,%2,%3}, {%4,%5,%6,%7}, {%8,%9}, {%0,%1,%2,%3};"
        : "+f"(d[0]), "+f"(d[1]), "+f"(d[2]), "+f"(d[3])
        : "r"(a[0]), "r"(a[1]), "r"(a[2]), "r"(a[3]), "r"(b0), "r"(b1));
}

// ---------------- fp32 -> fp16 conversion pass -------------------------------
__global__ void to_half_kernel(const float* __restrict__ src,
                               __half* __restrict__ dst, int n4) {
    int i = blockIdx.x * blockDim.x + threadIdx.x;
    int stride = gridDim.x * blockDim.x;
    for (; i < n4; i += stride) {
        float4 v = ((const float4*)src)[i];
        ((__half2*)dst)[2 * i]     = __floats2half2_rn(v.x, v.y);
        ((__half2*)dst)[2 * i + 1] = __floats2half2_rn(v.z, v.w);
    }
}

// ---------------- fp16 mma.sync GEMM ------------------------------------------
// C[M,N] = act(A[M,K] @ W[N,K]^T + bias). Tile 128x128x64, cp.async double buf,
// 256 threads, warp grid 4(M) x 2(N), warp tile 32x64, atoms m16n8k16 + ldmatrix.
#define BM 128
#define BN 128
#define BK 64
#define ROWB 144                       // padded row bytes (72 halfs)
#define ATILE_B (128 * ROWB)           // 18432 B per operand tile
#define BUF_B   (2 * ATILE_B)          // 36864 B per buffer
#define SMEM_TOTAL (2 * BUF_B)         // 73728 B

template <int ACT, typename OutT>      // ACT: 0 none, 1 relu, 2 tanh
__global__ void __launch_bounds__(256)
gemm_h(const __half* __restrict__ A, const __half* __restrict__ W,
       const float* __restrict__ bias, OutT* __restrict__ C,
       int M, int N, int K)
{
    extern __shared__ char smc[];
    const uint32_t sb = smem_u32(smc);
    const int tid  = threadIdx.x;
    const int wid  = tid >> 5, lane = tid & 31;
    const int g    = lane >> 2, c = lane & 3;
    const int wm   = wid & 3, wn = wid >> 2;
    const int bm   = blockIdx.x * BM;
    const int bn   = blockIdx.y * BN;

    // loader: thread -> row (tid>>1), 64-byte half-row (tid&1); 4x cp.async16
    const int lrow = tid >> 1;
    const int lsel = tid & 1;
    const __half* Ag = A + (size_t)(bm + lrow) * K + lsel * 32;
    const __half* Bg = W + (size_t)(bn + lrow) * K + lsel * 32;
    const uint32_t stA = sb + (uint32_t)(lrow * ROWB + lsel * 64);
    const uint32_t stB = stA + ATILE_B;

    float acc[2][8][4];
#pragma unroll
    for (int mt = 0; mt < 2; mt++)
#pragma unroll
        for (int nt = 0; nt < 8; nt++)
#pragma unroll
            for (int r = 0; r < 4; r++) acc[mt][nt][r] = 0.0f;

    const int nk = K / BK;

    // prefetch tile 0 -> buffer 0
#pragma unroll
    for (int i = 0; i < 4; i++) {
        cp_async16(stA + i * 16, Ag + i * 8);
        cp_async16(stB + i * 16, Bg + i * 8);
    }
    cp_commit();

    // ldmatrix per-thread base offsets (bytes within tile)
    const uint32_t aBase = (uint32_t)((wm * 32 + (lane & 15)) * ROWB + (lane >> 4) * 16);
    const uint32_t bBase = (uint32_t)ATILE_B +
        (uint32_t)((wn * 64 + (lane & 7) + ((lane >> 4) << 3)) * ROWB +
                   ((lane >> 3) & 1) * 16);

    for (int it = 0; it < nk; ++it) {
        const int buf = it & 1;
        if (it + 1 < nk) {
            const uint32_t d = (uint32_t)(((it + 1) & 1) * BUF_B);
            const __half* Ap = Ag + (size_t)(it + 1) * BK;
            const __half* Bp = Bg + (size_t)(it + 1) * BK;
#pragma unroll
            for (int i = 0; i < 4; i++) {
                cp_async16(stA + d + i * 16, Ap + i * 8);
                cp_async16(stB + d + i * 16, Bp + i * 8);
            }
            cp_commit();
            cp_wait<1>();
        } else {
            cp_wait<0>();
        }
        __syncthreads();

        const uint32_t tb = sb + buf * BUF_B;
#pragma unroll
        for (int ks = 0; ks < 4; ++ks) {
            uint32_t a[2][4];
            ldsm4(a[0][0], a[0][1], a[0][2], a[0][3], tb + aBase + ks * 32);
            ldsm4(a[1][0], a[1][1], a[1][2], a[1][3],
                  tb + aBase + 16 * ROWB + ks * 32);
#pragma unroll
            for (int np = 0; np < 4; ++np) {
                uint32_t b0, b1, b2, b3;
                ldsm4(b0, b1, b2, b3, tb + bBase + np * 16 * ROWB + ks * 32);
                mma_f16(acc[0][2 * np],     a[0], b0, b1);
                mma_f16(acc[1][2 * np],     a[1], b0, b1);
                mma_f16(acc[0][2 * np + 1], a[0], b2, b3);
                mma_f16(acc[1][2 * np + 1], a[1], b2, b3);
            }
        }
        __syncthreads();
    }

    // epilogue: bias + activation; half2 or float2 stores
#pragma unroll
    for (int nt = 0; nt < 8; ++nt) {
        const int colb = bn + wn * 64 + nt * 8 + 2 * c;
        const float bz0 = bias[colb], bz1 = bias[colb + 1];
#pragma unroll
        for (int mt = 0; mt < 2; ++mt) {
            const int row0 = bm + wm * 32 + mt * 16 + g;
            float o0 = acc[mt][nt][0] + bz0;
            float o1 = acc[mt][nt][1] + bz1;
            float o2 = acc[mt][nt][2] + bz0;
            float o3 = acc[mt][nt][3] + bz1;
            if (ACT == 1) {
                o0 = fmaxf(o0, 0.f); o1 = fmaxf(o1, 0.f);
                o2 = fmaxf(o2, 0.f); o3 = fmaxf(o3, 0.f);
            }
            if (ACT == 2) {
                o0 = tanhf(o0); o1 = tanhf(o1);
                o2 = tanhf(o2); o3 = tanhf(o3);
            }
            if (sizeof(OutT) == 2) {
                __half2* p0 = (__half2*)((__half*)C + (size_t)row0 * N + colb);
                __half2* p1 = (__half2*)((__half*)C + (size_t)(row0 + 8) * N + colb);
                *p0 = __floats2half2_rn(o0, o1);
                *p1 = __floats2half2_rn(o2, o3);
            } else {
                *(float2*)((float*)C + (size_t)row0 * N + colb) = make_float2(o0, o1);
                *(float2*)((float*)C + (size_t)(row0 + 8) * N + colb) = make_float2(o2, o3);
            }
        }
    }
}

// ---------------- per-row channel: norm -> fade+noise -> LS -> ZF ----------
__device__ __forceinline__ float blockReduce128(float v, volatile float* sm)
{
#pragma unroll
    for (int o = 16; o; o >>= 1) v += __shfl_down_sync(0xffffffffu, v, o);
    int lane = threadIdx.x & 31, warp = threadIdx.x >> 5;
    __syncthreads();
    if (lane == 0) sm[warp] = v;
    __syncthreads();
    return sm[0] + sm[1] + sm[2] + sm[3];
}

__global__ void channel_kernel(const __half* __restrict__ s,
                               const float* __restrict__ noise,
                               const float* __restrict__ h,
                               __half* __restrict__ xr)
{
    __shared__ float sm[4];
    const int row = blockIdx.x;
    const int t = threadIdx.x;

    float2 sp = __half22float2(*(const __half2*)(s + (size_t)row * CH + 2 * t));
    float sumsq = blockReduce128(sp.x * sp.x + sp.y * sp.y, sm);
    float scale = sqrtf(128.0f) * rsqrtf(sumsq);
    float txr = scale * sp.x, txi = scale * sp.y;

    float h0 = h[0], h1 = h[1];
    float2 np = *(const float2*)(noise + (size_t)row * CH + 2 * t);
    float yr = h0 * txr - h1 * txi + np.x;
    float yi = h0 * txi + h1 * txr + np.y;

    float numr = blockReduce128(yr * txr + yi * txi, sm);
    float numi = blockReduce128(yi * txr - yr * txi, sm);
    float den  = blockReduce128(txr * txr + txi * txi, sm);

    float hr = numr / den, hi = numi / den;
    float d2 = hr * hr + hi * hi + 1e-12f;
    float xe_r = (yr * hr + yi * hi) / d2;
    float xe_i = (yi * hr - yr * hi) / d2;
    *(__half2*)(xr + (size_t)row * CH + 2 * t) = __floats2half2_rn(xe_r, xe_i);
}

// ---------------- RTN tail: h_inv = g2 @ w_rtn3^T + b; 3-tap complex conv --
__global__ void __launch_bounds__(256)
rtn_tail(const __half* __restrict__ g2, const float* __restrict__ w_rtn3,
         const float* __restrict__ b_rtn3, const __half* __restrict__ xr,
         __half* __restrict__ xr2)
{
    __shared__ float gs[HR];
    __shared__ float xs[CH];
    __shared__ float red[6][8];
    __shared__ float hinv[6];

    const int row = blockIdx.x, tid = threadIdx.x;
    for (int i = tid; i < HR; i += 256) gs[i] = __half2float(g2[(size_t)row * HR + i]);
    for (int i = tid; i < CH; i += 256) xs[i] = __half2float(xr[(size_t)row * CH + i]);
    __syncthreads();

    float acc[6] = {0, 0, 0, 0, 0, 0};
    for (int i = tid; i < HR; i += 256) {
        float gv = gs[i];
#pragma unroll
        for (int o = 0; o < 6; o++) acc[o] += gv * w_rtn3[o * HR + i];
    }
#pragma unroll
    for (int o = 0; o < 6; o++) {
        float v = acc[o];
#pragma unroll
        for (int sft = 16; sft; sft >>= 1) v += __shfl_down_sync(0xffffffffu, v, sft);
        if ((tid & 31) == 0) red[o][tid >> 5] = v;
    }
    __syncthreads();
    if (tid < 6) {
        float v = 0;
#pragma unroll
        for (int w = 0; w < 8; w++) v += red[tid][w];
        hinv[tid] = v + b_rtn3[tid];
    }
    __syncthreads();

    if (tid < 128) {
        float or_ = 0.0f, oi_ = 0.0f;
#pragma unroll
        for (int l = 0; l < 3; l++) {
            if (tid - l >= 0) {
                float hrr = hinv[2 * l], hii = hinv[2 * l + 1];
                float xrr = xs[2 * (tid - l)], xii = xs[2 * (tid - l) + 1];
                or_ += hrr * xrr - hii * xii;
                oi_ += hrr * xii + hii * xrr;
            }
        }
        *(__half2*)(xr2 + (size_t)row * CH + 2 * tid) = __floats2half2_rn(or_, oi_);
    }
}

// ---------------- launcher --------------------------------------------------
extern "C" void kernel_launch(void* const* d_in, const int* in_sizes, int n_in,
                              void* d_out, int out_size)
{
    const float* x     = (const float*)d_in[0];
    const float* w1    = (const float*)d_in[1];
    const float* b1    = (const float*)d_in[2];
    const float* w2    = (const float*)d_in[3];
    const float* b2    = (const float*)d_in[4];
    const float* wr1   = (const float*)d_in[5];
    const float* br1   = (const float*)d_in[6];
    const float* wr2   = (const float*)d_in[7];
    const float* br2   = (const float*)d_in[8];
    const float* wr3   = (const float*)d_in[9];
    const float* br3   = (const float*)d_in[10];
    const float* w3    = (const float*)d_in[11];
    const float* b3    = (const float*)d_in[12];
    const float* w4    = (const float*)d_in[13];
    const float* b4    = (const float*)d_in[14];
    const float* h     = (const float*)d_in[15];
    const float* noise = (const float*)d_in[16];

    __half *xh, *wh, *ah, *sh, *xrh, *g1h, *g2h, *x2h, *th;
    cudaGetSymbolAddress((void**)&xh,  g_xh);
    cudaGetSymbolAddress((void**)&wh,  g_wh);
    cudaGetSymbolAddress((void**)&ah,  g_ah);
    cudaGetSymbolAddress((void**)&sh,  g_sh);
    cudaGetSymbolAddress((void**)&xrh, g_xrh);
    cudaGetSymbolAddress((void**)&g1h, g_g1h);
    cudaGetSymbolAddress((void**)&g2h, g_g2h);
    cudaGetSymbolAddress((void**)&x2h, g_x2h);
    cudaGetSymbolAddress((void**)&th,  g_th);

    cudaFuncSetAttribute(gemm_h<1, __half>, cudaFuncAttributeMaxDynamicSharedMemorySize, SMEM_TOTAL);
    cudaFuncSetAttribute(gemm_h<0, __half>, cudaFuncAttributeMaxDynamicSharedMemorySize, SMEM_TOTAL);
    cudaFuncSetAttribute(gemm_h<2, __half>, cudaFuncAttributeMaxDynamicSharedMemorySize, SMEM_TOTAL);
    cudaFuncSetAttribute(gemm_h<0, float>,  cudaFuncAttributeMaxDynamicSharedMemorySize, SMEM_TOTAL);

    // fp32 -> fp16 (RN) conversions
    to_half_kernel<<<1024, 256>>>(x,   xh,            BB * D_IN / 4);
    to_half_kernel<<<1024, 256>>>(w1,  wh + OFF_W1,   H1 * D_IN / 4);
    to_half_kernel<<<1024, 256>>>(w2,  wh + OFF_W2,   CH * H1 / 4);
    to_half_kernel<<<256,  256>>>(wr1, wh + OFF_WR1,  HR * CH / 4);
    to_half_kernel<<<1024, 256>>>(wr2, wh + OFF_WR2,  HR * HR / 4);
    to_half_kernel<<<1024, 256>>>(w3,  wh + OFF_W3,   H2 * CH / 4);
    to_half_kernel<<<1024, 256>>>(w4,  wh + OFF_W4,   D_OUTN * H2 / 4);

    // encoder
    gemm_h<1, __half><<<dim3(BB / BM, H1 / BN), 256, SMEM_TOTAL>>>(
        xh, wh + OFF_W1, b1, ah, BB, H1, D_IN);
    gemm_h<0, __half><<<dim3(BB / BM, CH / BN), 256, SMEM_TOTAL>>>(
        ah, wh + OFF_W2, b2, sh, BB, CH, H1);
    // channel + equalization
    channel_kernel<<<BB, 128>>>(sh, noise, h, xrh);
    // RTN
    gemm_h<2, __half><<<dim3(BB / BM, HR / BN), 256, SMEM_TOTAL>>>(
        xrh, wh + OFF_WR1, br1, g1h, BB, HR, CH);
    gemm_h<2, __half><<<dim3(BB / BM, HR / BN), 256, SMEM_TOTAL>>>(
        g1h, wh + OFF_WR2, br2, g2h, BB, HR, HR);
    rtn_tail<<<BB, 256>>>(g2h, wr3, br3, xrh, x2h);
    // decoder
    gemm_h<1, __half><<<dim3(BB / BM, H2 / BN), 256, SMEM_TOTAL>>>(
        x2h, wh + OFF_W3, b3, th, BB, H2, CH);
    gemm_h<0, float><<<dim3(BB / BM, D_OUTN / BN), 256, SMEM_TOTAL>>>(
        th, wh + OFF_W4, b4, (float*)d_out, BB, D_OUTN, H2);
}

// round 5
// speedup vs baseline: 4.5708x; 1.0576x over previous
#include <cuda_runtime.h>
#include <cuda_fp16.h>
#include <cstdint>
#include <math.h>

#define BB    8192
#define D_IN  512
#define H1    4096
#define CH    256
#define HR    1024
#define H2    4096
#define D_OUTN 512

// ---------------- scratch (device globals; no allocation allowed) ----------
__device__ __half g_xh [(size_t)BB * D_IN];
__device__ __half g_wh [(size_t)7602176];       // all weights, fp16
__device__ __half g_ah [(size_t)BB * H1];
__device__ __half g_sh [(size_t)BB * CH];
__device__ __half g_xrh[(size_t)BB * CH];
__device__ __half g_g1h[(size_t)BB * HR];
__device__ __half g_g2h[(size_t)BB * HR];
__device__ __half g_x2h[(size_t)BB * CH];
__device__ __half g_th [(size_t)BB * H2];

#define OFF_W1  0
#define OFF_W2  2097152
#define OFF_WR1 3145728
#define OFF_WR2 3407872
#define OFF_W3  4456448
#define OFF_W4  5505024

// ---------------- helpers ----------------------------------------------------
__device__ __forceinline__ uint32_t smem_u32(const void* p) {
    uint32_t a;
    asm("{ .reg .u64 t; cvta.to.shared.u64 t, %1; cvt.u32.u64 %0, t; }"
        : "=r"(a) : "l"(p));
    return a;
}

__device__ __forceinline__ void cp_async16(uint32_t dst, const void* src) {
    asm volatile("cp.async.cg.shared.global [%0], [%1], 16;"
        :: "r"(dst), "l"(src) : "memory");
}
__device__ __forceinline__ void cp_commit() {
    asm volatile("cp.async.commit_group;" ::: "memory");
}
template <int N>
__device__ __forceinline__ void cp_wait() {
    asm volatile("cp.async.wait_group %0;" :: "n"(N) : "memory");
}

__device__ __forceinline__ void ldsm4(uint32_t& r0, uint32_t& r1,
                                      uint32_t& r2, uint32_t& r3, uint32_t a) {
    asm volatile("ldmatrix.sync.aligned.m8n8.x4.shared.b16 {%0,%1,%2,%3}, [%4];"
        : "=r"(r0), "=r"(r1), "=r"(r2), "=r"(r3) : "r"(a));
}

__device__ __forceinline__ void mma_f16(float* d, const uint32_t* a,
                                        uint32_t b0, uint32_t b1) {
    asm volatile(
        "mma.sync.aligned.m16n8k16.row.col.f32.f16.f16.f32 "
        "{%0,%1,%2,%3}, {%4,%5,%6,%7}, {%8,%9}, {%0,%1,%2,%3};"
        : "+f"(d[0]), "+f"(d[1]), "+f"(d[2]), "+f"(d[3])
        : "r"(a[0]), "r"(a[1]), "r"(a[2]), "r"(a[3]), "r"(b0), "r"(b1));
}

// ---------------- fp32 -> fp16 conversion pass -------------------------------
__global__ void to_half_kernel(const float* __restrict__ src,
                               __half* __restrict__ dst, int n4) {
    int i = blockIdx.x * blockDim.x + threadIdx.x;
    int stride = gridDim.x * blockDim.x;
    for (; i < n4; i += stride) {
        float4 v = ((const float4*)src)[i];
        ((__half2*)dst)[2 * i]     = __floats2half2_rn(v.x, v.y);
        ((__half2*)dst)[2 * i + 1] = __floats2half2_rn(v.z, v.w);
    }
}

// =============== WIDE fp16 GEMM: 128x256x64, 3-stage, warp tile 64x64 ========
#define WROWB 144                     // padded row bytes (72 halfs)
#define WA_B  (128 * WROWB)           // 18432
#define WB_B  (256 * WROWB)           // 36864
#define WSTAGE (WA_B + WB_B)          // 55296
#define WSMEM  (3 * WSTAGE)           // 165888

template <int ACT, typename OutT>     // ACT: 0 none, 1 relu, 2 tanh
__global__ void __launch_bounds__(256, 1)
gemm_w(const __half* __restrict__ A, const __half* __restrict__ W,
       const float* __restrict__ bias, OutT* __restrict__ C,
       int M, int N, int K)
{
    extern __shared__ char smc[];
    const uint32_t sb = smem_u32(smc);
    const int tid  = threadIdx.x;
    const int wid  = tid >> 5, lane = tid & 31;
    const int g    = lane >> 2, c = lane & 3;
    const int wm   = wid & 1, wn = wid >> 1;      // warp grid 2(M) x 4(N)
    const int bm   = blockIdx.x * 128;
    const int bn   = blockIdx.y * 256;

    const int lrow = tid >> 1;
    const int lsel = tid & 1;
    const __half* Ag  = A + (size_t)(bm + lrow) * K + lsel * 32;
    const __half* Bg0 = W + (size_t)(bn + lrow) * K + lsel * 32;
    const __half* Bg1 = Bg0 + (size_t)128 * K;
    const uint32_t stA  = sb + (uint32_t)(lrow * WROWB + lsel * 64);
    const uint32_t stB0 = sb + WA_B + (uint32_t)(lrow * WROWB + lsel * 64);
    const uint32_t stB1 = stB0 + 128 * WROWB;

    float acc[4][8][4];
#pragma unroll
    for (int mt = 0; mt < 4; mt++)
#pragma unroll
        for (int nt = 0; nt < 8; nt++)
#pragma unroll
            for (int r = 0; r < 4; r++) acc[mt][nt][r] = 0.0f;

    const int nk = K / 64;

    // prefetch stages 0,1
#pragma unroll
    for (int s = 0; s < 2; ++s) {
        const uint32_t base = s * WSTAGE;
        const int off = s * 64;
#pragma unroll
        for (int i = 0; i < 4; i++) {
            cp_async16(stA  + base + i * 16, Ag  + off + i * 8);
            cp_async16(stB0 + base + i * 16, Bg0 + off + i * 8);
            cp_async16(stB1 + base + i * 16, Bg1 + off + i * 8);
        }
        cp_commit();
    }

    const uint32_t aBase = (uint32_t)((wm * 64 + (lane & 15)) * WROWB +
                                      (lane >> 4) * 16);
    const uint32_t bBase = (uint32_t)WA_B +
        (uint32_t)((wn * 64 + (lane & 7) + ((lane >> 4) << 3)) * WROWB +
                   ((lane >> 3) & 1) * 16);

    int stage = 0, nstage = 2;
    for (int it = 0; it < nk; ++it) {
        cp_wait<1>();
        __syncthreads();

        // issue stage it+2 (or an empty commit to keep group counting uniform)
        if (it + 2 < nk) {
            const uint32_t base = nstage * WSTAGE;
            const int off = (it + 2) * 64;
#pragma unroll
            for (int i = 0; i < 4; i++) {
                cp_async16(stA  + base + i * 16, Ag  + off + i * 8);
                cp_async16(stB0 + base + i * 16, Bg0 + off + i * 8);
                cp_async16(stB1 + base + i * 16, Bg1 + off + i * 8);
            }
        }
        cp_commit();
        nstage = nstage + 1 == 3 ? 0 : nstage + 1;

        const uint32_t tb = sb + stage * WSTAGE;
        stage = stage + 1 == 3 ? 0 : stage + 1;
#pragma unroll
        for (int ks = 0; ks < 4; ++ks) {
            uint32_t a[4][4];
#pragma unroll
            for (int mt = 0; mt < 4; ++mt)
                ldsm4(a[mt][0], a[mt][1], a[mt][2], a[mt][3],
                      tb + aBase + mt * 16 * WROWB + ks * 32);
#pragma unroll
            for (int np = 0; np < 4; ++np) {
                uint32_t b0, b1, b2, b3;
                ldsm4(b0, b1, b2, b3, tb + bBase + np * 16 * WROWB + ks * 32);
#pragma unroll
                for (int mt = 0; mt < 4; ++mt) {
                    mma_f16(acc[mt][2 * np],     a[mt], b0, b1);
                    mma_f16(acc[mt][2 * np + 1], a[mt], b2, b3);
                }
            }
        }
    }

    // epilogue
#pragma unroll
    for (int nt = 0; nt < 8; ++nt) {
        const int colb = bn + wn * 64 + nt * 8 + 2 * c;
        const float bz0 = bias[colb], bz1 = bias[colb + 1];
#pragma unroll
        for (int mt = 0; mt < 4; ++mt) {
            const int row0 = bm + wm * 64 + mt * 16 + g;
            float o0 = acc[mt][nt][0] + bz0;
            float o1 = acc[mt][nt][1] + bz1;
            float o2 = acc[mt][nt][2] + bz0;
            float o3 = acc[mt][nt][3] + bz1;
            if (ACT == 1) {
                o0 = fmaxf(o0, 0.f); o1 = fmaxf(o1, 0.f);
                o2 = fmaxf(o2, 0.f); o3 = fmaxf(o3, 0.f);
            }
            if (ACT == 2) {
                o0 = tanhf(o0); o1 = tanhf(o1);
                o2 = tanhf(o2); o3 = tanhf(o3);
            }
            if (sizeof(OutT) == 2) {
                *(__half2*)((__half*)C + (size_t)row0 * N + colb) =
                    __floats2half2_rn(o0, o1);
                *(__half2*)((__half*)C + (size_t)(row0 + 8) * N + colb) =
                    __floats2half2_rn(o2, o3);
            } else {
                *(float2*)((float*)C + (size_t)row0 * N + colb) = make_float2(o0, o1);
                *(float2*)((float*)C + (size_t)(row0 + 8) * N + colb) = make_float2(o2, o3);
            }
        }
    }
}

// =============== narrow fp16 GEMM (for N=256): 128x128x64, 2-stage ===========
#define BM 128
#define BN 128
#define BK 64
#define ROWB 144
#define ATILE_B (128 * ROWB)
#define BUF_B   (2 * ATILE_B)
#define SMEM_TOTAL (2 * BUF_B)

template <int ACT, typename OutT>
__global__ void __launch_bounds__(256)
gemm_h(const __half* __restrict__ A, const __half* __restrict__ W,
       const float* __restrict__ bias, OutT* __restrict__ C,
       int M, int N, int K)
{
    extern __shared__ char smc[];
    const uint32_t sb = smem_u32(smc);
    const int tid  = threadIdx.x;
    const int wid  = tid >> 5, lane = tid & 31;
    const int g    = lane >> 2, c = lane & 3;
    const int wm   = wid & 3, wn = wid >> 2;
    const int bm   = blockIdx.x * BM;
    const int bn   = blockIdx.y * BN;

    const int lrow = tid >> 1;
    const int lsel = tid & 1;
    const __half* Ag = A + (size_t)(bm + lrow) * K + lsel * 32;
    const __half* Bg = W + (size_t)(bn + lrow) * K + lsel * 32;
    const uint32_t stA = sb + (uint32_t)(lrow * ROWB + lsel * 64);
    const uint32_t stB = stA + ATILE_B;

    float acc[2][8][4];
#pragma unroll
    for (int mt = 0; mt < 2; mt++)
#pragma unroll
        for (int nt = 0; nt < 8; nt++)
#pragma unroll
            for (int r = 0; r < 4; r++) acc[mt][nt][r] = 0.0f;

    const int nk = K / BK;

#pragma unroll
    for (int i = 0; i < 4; i++) {
        cp_async16(stA + i * 16, Ag + i * 8);
        cp_async16(stB + i * 16, Bg + i * 8);
    }
    cp_commit();

    const uint32_t aBase = (uint32_t)((wm * 32 + (lane & 15)) * ROWB + (lane >> 4) * 16);
    const uint32_t bBase = (uint32_t)ATILE_B +
        (uint32_t)((wn * 64 + (lane & 7) + ((lane >> 4) << 3)) * ROWB +
                   ((lane >> 3) & 1) * 16);

    for (int it = 0; it < nk; ++it) {
        const int buf = it & 1;
        if (it + 1 < nk) {
            const uint32_t d = (uint32_t)(((it + 1) & 1) * BUF_B);
            const __half* Ap = Ag + (size_t)(it + 1) * BK;
            const __half* Bp = Bg + (size_t)(it + 1) * BK;
#pragma unroll
            for (int i = 0; i < 4; i++) {
                cp_async16(stA + d + i * 16, Ap + i * 8);
                cp_async16(stB + d + i * 16, Bp + i * 8);
            }
            cp_commit();
            cp_wait<1>();
        } else {
            cp_wait<0>();
        }
        __syncthreads();

        const uint32_t tb = sb + buf * BUF_B;
#pragma unroll
        for (int ks = 0; ks < 4; ++ks) {
            uint32_t a[2][4];
            ldsm4(a[0][0], a[0][1], a[0][2], a[0][3], tb + aBase + ks * 32);
            ldsm4(a[1][0], a[1][1], a[1][2], a[1][3],
                  tb + aBase + 16 * ROWB + ks * 32);
#pragma unroll
            for (int np = 0; np < 4; ++np) {
                uint32_t b0, b1, b2, b3;
                ldsm4(b0, b1, b2, b3, tb + bBase + np * 16 * ROWB + ks * 32);
                mma_f16(acc[0][2 * np],     a[0], b0, b1);
                mma_f16(acc[1][2 * np],     a[1], b0, b1);
                mma_f16(acc[0][2 * np + 1], a[0], b2, b3);
                mma_f16(acc[1][2 * np + 1], a[1], b2, b3);
            }
        }
        __syncthreads();
    }

#pragma unroll
    for (int nt = 0; nt < 8; ++nt) {
        const int colb = bn + wn * 64 + nt * 8 + 2 * c;
        const float bz0 = bias[colb], bz1 = bias[colb + 1];
#pragma unroll
        for (int mt = 0; mt < 2; ++mt) {
            const int row0 = bm + wm * 32 + mt * 16 + g;
            float o0 = acc[mt][nt][0] + bz0;
            float o1 = acc[mt][nt][1] + bz1;
            float o2 = acc[mt][nt][2] + bz0;
            float o3 = acc[mt][nt][3] + bz1;
            if (ACT == 1) {
                o0 = fmaxf(o0, 0.f); o1 = fmaxf(o1, 0.f);
                o2 = fmaxf(o2, 0.f); o3 = fmaxf(o3, 0.f);
            }
            if (ACT == 2) {
                o0 = tanhf(o0); o1 = tanhf(o1);
                o2 = tanhf(o2); o3 = tanhf(o3);
            }
            if (sizeof(OutT) == 2) {
                *(__half2*)((__half*)C + (size_t)row0 * N + colb) =
                    __floats2half2_rn(o0, o1);
                *(__half2*)((__half*)C + (size_t)(row0 + 8) * N + colb) =
                    __floats2half2_rn(o2, o3);
            } else {
                *(float2*)((float*)C + (size_t)row0 * N + colb) = make_float2(o0, o1);
                *(float2*)((float*)C + (size_t)(row0 + 8) * N + colb) = make_float2(o2, o3);
            }
        }
    }
}

// ---------------- per-row channel: norm -> fade+noise -> LS -> ZF ----------
__device__ __forceinline__ float blockReduce128(float v, volatile float* sm)
{
#pragma unroll
    for (int o = 16; o; o >>= 1) v += __shfl_down_sync(0xffffffffu, v, o);
    int lane = threadIdx.x & 31, warp = threadIdx.x >> 5;
    __syncthreads();
    if (lane == 0) sm[warp] = v;
    __syncthreads();
    return sm[0] + sm[1] + sm[2] + sm[3];
}

__global__ void channel_kernel(const __half* __restrict__ s,
                               const float* __restrict__ noise,
                               const float* __restrict__ h,
                               __half* __restrict__ xr)
{
    __shared__ float sm[4];
    const int row = blockIdx.x;
    const int t = threadIdx.x;

    float2 sp = __half22float2(*(const __half2*)(s + (size_t)row * CH + 2 * t));
    float sumsq = blockReduce128(sp.x * sp.x + sp.y * sp.y, sm);
    float scale = sqrtf(128.0f) * rsqrtf(sumsq);
    float txr = scale * sp.x, txi = scale * sp.y;

    float h0 = h[0], h1 = h[1];
    float2 np = *(const float2*)(noise + (size_t)row * CH + 2 * t);
    float yr = h0 * txr - h1 * txi + np.x;
    float yi = h0 * txi + h1 * txr + np.y;

    float numr = blockReduce128(yr * txr + yi * txi, sm);
    float numi = blockReduce128(yi * txr - yr * txi, sm);
    float den  = blockReduce128(txr * txr + txi * txi, sm);

    float hr = numr / den, hi = numi / den;
    float d2 = hr * hr + hi * hi + 1e-12f;
    float xe_r = (yr * hr + yi * hi) / d2;
    float xe_i = (yi * hr - yr * hi) / d2;
    *(__half2*)(xr + (size_t)row * CH + 2 * t) = __floats2half2_rn(xe_r, xe_i);
}

// ---------------- RTN tail: h_inv = g2 @ w_rtn3^T + b; 3-tap complex conv --
__global__ void __launch_bounds__(256)
rtn_tail(const __half* __restrict__ g2, const float* __restrict__ w_rtn3,
         const float* __restrict__ b_rtn3, const __half* __restrict__ xr,
         __half* __restrict__ xr2)
{
    __shared__ float gs[HR];
    __shared__ float xs[CH];
    __shared__ float red[6][8];
    __shared__ float hinv[6];

    const int row = blockIdx.x, tid = threadIdx.x;
    for (int i = tid; i < HR; i += 256) gs[i] = __half2float(g2[(size_t)row * HR + i]);
    for (int i = tid; i < CH; i += 256) xs[i] = __half2float(xr[(size_t)row * CH + i]);
    __syncthreads();

    float acc[6] = {0, 0, 0, 0, 0, 0};
    for (int i = tid; i < HR; i += 256) {
        float gv = gs[i];
#pragma unroll
        for (int o = 0; o < 6; o++) acc[o] += gv * w_rtn3[o * HR + i];
    }
#pragma unroll
    for (int o = 0; o < 6; o++) {
        float v = acc[o];
#pragma unroll
        for (int sft = 16; sft; sft >>= 1) v += __shfl_down_sync(0xffffffffu, v, sft);
        if ((tid & 31) == 0) red[o][tid >> 5] = v;
    }
    __syncthreads();
    if (tid < 6) {
        float v = 0;
#pragma unroll
        for (int w = 0; w < 8; w++) v += red[tid][w];
        hinv[tid] = v + b_rtn3[tid];
    }
    __syncthreads();

    if (tid < 128) {
        float or_ = 0.0f, oi_ = 0.0f;
#pragma unroll
        for (int l = 0; l < 3; l++) {
            if (tid - l >= 0) {
                float hrr = hinv[2 * l], hii = hinv[2 * l + 1];
                float xrr = xs[2 * (tid - l)], xii = xs[2 * (tid - l) + 1];
                or_ += hrr * xrr - hii * xii;
                oi_ += hrr * xii + hii * xrr;
            }
        }
        *(__half2*)(xr2 + (size_t)row * CH + 2 * tid) = __floats2half2_rn(or_, oi_);
    }
}

// ---------------- launcher --------------------------------------------------
extern "C" void kernel_launch(void* const* d_in, const int* in_sizes, int n_in,
                              void* d_out, int out_size)
{
    const float* x     = (const float*)d_in[0];
    const float* w1    = (const float*)d_in[1];
    const float* b1    = (const float*)d_in[2];
    const float* w2    = (const float*)d_in[3];
    const float* b2    = (const float*)d_in[4];
    const float* wr1   = (const float*)d_in[5];
    const float* br1   = (const float*)d_in[6];
    const float* wr2   = (const float*)d_in[7];
    const float* br2   = (const float*)d_in[8];
    const float* wr3   = (const float*)d_in[9];
    const float* br3   = (const float*)d_in[10];
    const float* w3    = (const float*)d_in[11];
    const float* b3    = (const float*)d_in[12];
    const float* w4    = (const float*)d_in[13];
    const float* b4    = (const float*)d_in[14];
    const float* h     = (const float*)d_in[15];
    const float* noise = (const float*)d_in[16];

    __half *xh, *wh, *ah, *sh, *xrh, *g1h, *g2h, *x2h, *th;
    cudaGetSymbolAddress((void**)&xh,  g_xh);
    cudaGetSymbolAddress((void**)&wh,  g_wh);
    cudaGetSymbolAddress((void**)&ah,  g_ah);
    cudaGetSymbolAddress((void**)&sh,  g_sh);
    cudaGetSymbolAddress((void**)&xrh, g_xrh);
    cudaGetSymbolAddress((void**)&g1h, g_g1h);
    cudaGetSymbolAddress((void**)&g2h, g_g2h);
    cudaGetSymbolAddress((void**)&x2h, g_x2h);
    cudaGetSymbolAddress((void**)&th,  g_th);

    cudaFuncSetAttribute(gemm_w<1, __half>, cudaFuncAttributeMaxDynamicSharedMemorySize, WSMEM);
    cudaFuncSetAttribute(gemm_w<2, __half>, cudaFuncAttributeMaxDynamicSharedMemorySize, WSMEM);
    cudaFuncSetAttribute(gemm_w<0, float>,  cudaFuncAttributeMaxDynamicSharedMemorySize, WSMEM);
    cudaFuncSetAttribute(gemm_h<0, __half>, cudaFuncAttributeMaxDynamicSharedMemorySize, SMEM_TOTAL);

    // fp32 -> fp16 (RN) conversions
    to_half_kernel<<<1024, 256>>>(x,   xh,            BB * D_IN / 4);
    to_half_kernel<<<1024, 256>>>(w1,  wh + OFF_W1,   H1 * D_IN / 4);
    to_half_kernel<<<1024, 256>>>(w2,  wh + OFF_W2,   CH * H1 / 4);
    to_half_kernel<<<256,  256>>>(wr1, wh + OFF_WR1,  HR * CH / 4);
    to_half_kernel<<<1024, 256>>>(wr2, wh + OFF_WR2,  HR * HR / 4);
    to_half_kernel<<<1024, 256>>>(w3,  wh + OFF_W3,   H2 * CH / 4);
    to_half_kernel<<<1024, 256>>>(w4,  wh + OFF_W4,   D_OUTN * H2 / 4);

    // encoder
    gemm_w<1, __half><<<dim3(BB / 128, H1 / 256), 256, WSMEM>>>(
        xh, wh + OFF_W1, b1, ah, BB, H1, D_IN);
    gemm_h<0, __half><<<dim3(BB / BM, CH / BN), 256, SMEM_TOTAL>>>(
        ah, wh + OFF_W2, b2, sh, BB, CH, H1);
    // channel + equalization
    channel_kernel<<<BB, 128>>>(sh, noise, h, xrh);
    // RTN
    gemm_w<2, __half><<<dim3(BB / 128, HR / 256), 256, WSMEM>>>(
        xrh, wh + OFF_WR1, br1, g1h, BB, HR, CH);
    gemm_w<2, __half><<<dim3(BB / 128, HR / 256), 256, WSMEM>>>(
        g1h, wh + OFF_WR2, br2, g2h, BB, HR, HR);
    rtn_tail<<<BB, 256>>>(g2h, wr3, br3, xrh, x2h);
    // decoder
    gemm_w<1, __half><<<dim3(BB / 128, H2 / 256), 256, WSMEM>>>(
        x2h, wh + OFF_W3, b3, th, BB, H2, CH);
    gemm_w<0, float><<<dim3(BB / 128, D_OUTN / 256), 256, WSMEM>>>(
        th, wh + OFF_W4, b4, (float*)d_out, BB, D_OUTN, H2);
}

// round 6
// speedup vs baseline: 4.6783x; 1.0235x over previous
#include <cuda_runtime.h>
#include <cuda_fp16.h>
#include <cstdint>
#include <math.h>

#define BB    8192
#define D_IN  512
#define H1    4096
#define CH    256
#define HR    1024
#define H2    4096
#define D_OUTN 512

// ---------------- scratch (device globals; no allocation allowed) ----------
__device__ __half g_xh [(size_t)BB * D_IN];
__device__ __half g_wh [(size_t)7602176];       // all weights, fp16
__device__ __half g_ah [(size_t)BB * H1];
__device__ __half g_sh [(size_t)BB * CH];
__device__ __half g_xrh[(size_t)BB * CH];
__device__ __half g_g1h[(size_t)BB * HR];
__device__ __half g_g2h[(size_t)BB * HR];
__device__ __half g_x2h[(size_t)BB * CH];
__device__ __half g_th [(size_t)BB * H2];

#define OFF_W1  0
#define OFF_W2  2097152
#define OFF_WR1 3145728
#define OFF_WR2 3407872
#define OFF_W3  4456448
#define OFF_W4  5505024

// ---------------- helpers ----------------------------------------------------
__device__ __forceinline__ uint32_t smem_u32(const void* p) {
    uint32_t a;
    asm("{ .reg .u64 t; cvta.to.shared.u64 t, %1; cvt.u32.u64 %0, t; }"
        : "=r"(a) : "l"(p));
    return a;
}

__device__ __forceinline__ void cp_async16(uint32_t dst, const void* src) {
    asm volatile("cp.async.cg.shared.global [%0], [%1], 16;"
        :: "r"(dst), "l"(src) : "memory");
}
__device__ __forceinline__ void cp_commit() {
    asm volatile("cp.async.commit_group;" ::: "memory");
}
template <int N>
__device__ __forceinline__ void cp_wait() {
    asm volatile("cp.async.wait_group %0;" :: "n"(N) : "memory");
}

__device__ __forceinline__ void ldsm4(uint32_t& r0, uint32_t& r1,
                                      uint32_t& r2, uint32_t& r3, uint32_t a) {
    asm volatile("ldmatrix.sync.aligned.m8n8.x4.shared.b16 {%0,%1,%2,%3}, [%4];"
        : "=r"(r0), "=r"(r1), "=r"(r2), "=r"(r3) : "r"(a));
}

__device__ __forceinline__ void mma_f16(float* d, const uint32_t* a,
                                        uint32_t b0, uint32_t b1) {
    asm volatile(
        "mma.sync.aligned.m16n8k16.row.col.f32.f16.f16.f32 "
        "{%0,%1,%2,%3}, {%4,%5,%6,%7}, {%8,%9}, {%0,%1,%2,%3};"
        : "+f"(d[0]), "+f"(d[1]), "+f"(d[2]), "+f"(d[3])
        : "r"(a[0]), "r"(a[1]), "r"(a[2]), "r"(a[3]), "r"(b0), "r"(b1));
}

// ---------------- single fused fp32 -> fp16 conversion pass ------------------
struct ConvArgs {
    const float* src[8];
    __half*      dst[8];
    int          n4[8];     // element count / 4
};

__global__ void conv_all_kernel(ConvArgs a) {
    const int stride = gridDim.x * blockDim.x;
    const int t0 = blockIdx.x * blockDim.x + threadIdx.x;
#pragma unroll
    for (int s = 0; s < 8; ++s) {
        const float4* sp = (const float4*)a.src[s];
        __half2* dp = (__half2*)a.dst[s];
        const int n = a.n4[s];
        for (int i = t0; i < n; i += stride) {
            float4 v = sp[i];
            dp[2 * i]     = __floats2half2_rn(v.x, v.y);
            dp[2 * i + 1] = __floats2half2_rn(v.z, v.w);
        }
    }
}

// =============== fp16 GEMM: 128x128x64, 3-stage, 2 CTAs/SM ===================
#define BM 128
#define BN 128
#define BK 64
#define ROWB 144                      // padded row bytes (72 halfs)
#define ATILE_B (128 * ROWB)          // 18432
#define STAGE_B (2 * ATILE_B)         // 36864 (A + B)
#define SMEM3   (3 * STAGE_B)         // 110592

template <int ACT, typename OutT>     // ACT: 0 none, 1 relu, 2 tanh
__global__ void __launch_bounds__(256, 2)
gemm_h(const __half* __restrict__ A, const __half* __restrict__ W,
       const float* __restrict__ bias, OutT* __restrict__ C,
       int M, int N, int K)
{
    extern __shared__ char smc[];
    const uint32_t sb = smem_u32(smc);
    const int tid  = threadIdx.x;
    const int wid  = tid >> 5, lane = tid & 31;
    const int g    = lane >> 2, c = lane & 3;
    const int wm   = wid & 3, wn = wid >> 2;      // warp grid 4(M) x 2(N)
    const int bm   = blockIdx.x * BM;
    const int bn   = blockIdx.y * BN;

    const int lrow = tid >> 1;
    const int lsel = tid & 1;
    const __half* Ag = A + (size_t)(bm + lrow) * K + lsel * 32;
    const __half* Bg = W + (size_t)(bn + lrow) * K + lsel * 32;
    const uint32_t stA = sb + (uint32_t)(lrow * ROWB + lsel * 64);
    const uint32_t stB = stA + ATILE_B;

    float acc[2][8][4];
#pragma unroll
    for (int mt = 0; mt < 2; mt++)
#pragma unroll
        for (int nt = 0; nt < 8; nt++)
#pragma unroll
            for (int r = 0; r < 4; r++) acc[mt][nt][r] = 0.0f;

    const int nk = K / BK;

    // prefetch stages 0,1
#pragma unroll
    for (int s = 0; s < 2; ++s) {
        const uint32_t base = s * STAGE_B;
        const int off = s * BK;
#pragma unroll
        for (int i = 0; i < 4; i++) {
            cp_async16(stA + base + i * 16, Ag + off + i * 8);
            cp_async16(stB + base + i * 16, Bg + off + i * 8);
        }
        cp_commit();
    }

    const uint32_t aBase = (uint32_t)((wm * 32 + (lane & 15)) * ROWB + (lane >> 4) * 16);
    const uint32_t bBase = (uint32_t)ATILE_B +
        (uint32_t)((wn * 64 + (lane & 7) + ((lane >> 4) << 3)) * ROWB +
                   ((lane >> 3) & 1) * 16);

    int stage = 0, nstage = 2;
    for (int it = 0; it < nk; ++it) {
        cp_wait<1>();
        __syncthreads();

        if (it + 2 < nk) {
            const uint32_t base = nstage * STAGE_B;
            const int off = (it + 2) * BK;
#pragma unroll
            for (int i = 0; i < 4; i++) {
                cp_async16(stA + base + i * 16, Ag + off + i * 8);
                cp_async16(stB + base + i * 16, Bg + off + i * 8);
            }
        }
        cp_commit();
        nstage = nstage + 1 == 3 ? 0 : nstage + 1;

        const uint32_t tb = sb + stage * STAGE_B;
        stage = stage + 1 == 3 ? 0 : stage + 1;
#pragma unroll
        for (int ks = 0; ks < 4; ++ks) {
            uint32_t a[2][4];
            ldsm4(a[0][0], a[0][1], a[0][2], a[0][3], tb + aBase + ks * 32);
            ldsm4(a[1][0], a[1][1], a[1][2], a[1][3],
                  tb + aBase + 16 * ROWB + ks * 32);
#pragma unroll
            for (int np = 0; np < 4; ++np) {
                uint32_t b0, b1, b2, b3;
                ldsm4(b0, b1, b2, b3, tb + bBase + np * 16 * ROWB + ks * 32);
                mma_f16(acc[0][2 * np],     a[0], b0, b1);
                mma_f16(acc[1][2 * np],     a[1], b0, b1);
                mma_f16(acc[0][2 * np + 1], a[0], b2, b3);
                mma_f16(acc[1][2 * np + 1], a[1], b2, b3);
            }
        }
    }

    // epilogue: bias + activation
#pragma unroll
    for (int nt = 0; nt < 8; ++nt) {
        const int colb = bn + wn * 64 + nt * 8 + 2 * c;
        const float bz0 = bias[colb], bz1 = bias[colb + 1];
#pragma unroll
        for (int mt = 0; mt < 2; ++mt) {
            const int row0 = bm + wm * 32 + mt * 16 + g;
            float o0 = acc[mt][nt][0] + bz0;
            float o1 = acc[mt][nt][1] + bz1;
            float o2 = acc[mt][nt][2] + bz0;
            float o3 = acc[mt][nt][3] + bz1;
            if (ACT == 1) {
                o0 = fmaxf(o0, 0.f); o1 = fmaxf(o1, 0.f);
                o2 = fmaxf(o2, 0.f); o3 = fmaxf(o3, 0.f);
            }
            if (ACT == 2) {
                o0 = tanhf(o0); o1 = tanhf(o1);
                o2 = tanhf(o2); o3 = tanhf(o3);
            }
            if (sizeof(OutT) == 2) {
                *(__half2*)((__half*)C + (size_t)row0 * N + colb) =
                    __floats2half2_rn(o0, o1);
                *(__half2*)((__half*)C + (size_t)(row0 + 8) * N + colb) =
                    __floats2half2_rn(o2, o3);
            } else {
                *(float2*)((float*)C + (size_t)row0 * N + colb) = make_float2(o0, o1);
                *(float2*)((float*)C + (size_t)(row0 + 8) * N + colb) = make_float2(o2, o3);
            }
        }
    }
}

// ---------------- per-row channel: norm -> fade+noise -> LS -> ZF ----------
__device__ __forceinline__ float blockReduce128(float v, volatile float* sm)
{
#pragma unroll
    for (int o = 16; o; o >>= 1) v += __shfl_down_sync(0xffffffffu, v, o);
    int lane = threadIdx.x & 31, warp = threadIdx.x >> 5;
    __syncthreads();
    if (lane == 0) sm[warp] = v;
    __syncthreads();
    return sm[0] + sm[1] + sm[2] + sm[3];
}

__global__ void channel_kernel(const __half* __restrict__ s,
                               const float* __restrict__ noise,
                               const float* __restrict__ h,
                               __half* __restrict__ xr)
{
    __shared__ float sm[4];
    const int row = blockIdx.x;
    const int t = threadIdx.x;

    float2 sp = __half22float2(*(const __half2*)(s + (size_t)row * CH + 2 * t));
    float sumsq = blockReduce128(sp.x * sp.x + sp.y * sp.y, sm);
    float scale = sqrtf(128.0f) * rsqrtf(sumsq);
    float txr = scale * sp.x, txi = scale * sp.y;

    float h0 = h[0], h1 = h[1];
    float2 np = *(const float2*)(noise + (size_t)row * CH + 2 * t);
    float yr = h0 * txr - h1 * txi + np.x;
    float yi = h0 * txi + h1 * txr + np.y;

    float numr = blockReduce128(yr * txr + yi * txi, sm);
    float numi = blockReduce128(yi * txr - yr * txi, sm);
    float den  = blockReduce128(txr * txr + txi * txi, sm);

    float hr = numr / den, hi = numi / den;
    float d2 = hr * hr + hi * hi + 1e-12f;
    float xe_r = (yr * hr + yi * hi) / d2;
    float xe_i = (yi * hr - yr * hi) / d2;
    *(__half2*)(xr + (size_t)row * CH + 2 * t) = __floats2half2_rn(xe_r, xe_i);
}

// ---------------- RTN tail: h_inv = g2 @ w_rtn3^T + b; 3-tap complex conv --
__global__ void __launch_bounds__(256)
rtn_tail(const __half* __restrict__ g2, const float* __restrict__ w_rtn3,
         const float* __restrict__ b_rtn3, const __half* __restrict__ xr,
         __half* __restrict__ xr2)
{
    __shared__ float gs[HR];
    __shared__ float xs[CH];
    __shared__ float red[6][8];
    __shared__ float hinv[6];

    const int row = blockIdx.x, tid = threadIdx.x;
    for (int i = tid; i < HR; i += 256) gs[i] = __half2float(g2[(size_t)row * HR + i]);
    for (int i = tid; i < CH; i += 256) xs[i] = __half2float(xr[(size_t)row * CH + i]);
    __syncthreads();

    float acc[6] = {0, 0, 0, 0, 0, 0};
    for (int i = tid; i < HR; i += 256) {
        float gv = gs[i];
#pragma unroll
        for (int o = 0; o < 6; o++) acc[o] += gv * w_rtn3[o * HR + i];
    }
#pragma unroll
    for (int o = 0; o < 6; o++) {
        float v = acc[o];
#pragma unroll
        for (int sft = 16; sft; sft >>= 1) v += __shfl_down_sync(0xffffffffu, v, sft);
        if ((tid & 31) == 0) red[o][tid >> 5] = v;
    }
    __syncthreads();
    if (tid < 6) {
        float v = 0;
#pragma unroll
        for (int w = 0; w < 8; w++) v += red[tid][w];
        hinv[tid] = v + b_rtn3[tid];
    }
    __syncthreads();

    if (tid < 128) {
        float or_ = 0.0f, oi_ = 0.0f;
#pragma unroll
        for (int l = 0; l < 3; l++) {
            if (tid - l >= 0) {
                float hrr = hinv[2 * l], hii = hinv[2 * l + 1];
                float xrr = xs[2 * (tid - l)], xii = xs[2 * (tid - l) + 1];
                or_ += hrr * xrr - hii * xii;
                oi_ += hrr * xii + hii * xrr;
            }
        }
        *(__half2*)(xr2 + (size_t)row * CH + 2 * tid) = __floats2half2_rn(or_, oi_);
    }
}

// ---------------- launcher --------------------------------------------------
extern "C" void kernel_launch(void* const* d_in, const int* in_sizes, int n_in,
                              void* d_out, int out_size)
{
    const float* x     = (const float*)d_in[0];
    const float* w1    = (const float*)d_in[1];
    const float* b1    = (const float*)d_in[2];
    const float* w2    = (const float*)d_in[3];
    const float* b2    = (const float*)d_in[4];
    const float* wr1   = (const float*)d_in[5];
    const float* br1   = (const float*)d_in[6];
    const float* wr2   = (const float*)d_in[7];
    const float* br2   = (const float*)d_in[8];
    const float* wr3   = (const float*)d_in[9];
    const float* br3   = (const float*)d_in[10];
    const float* w3    = (const float*)d_in[11];
    const float* b3    = (const float*)d_in[12];
    const float* w4    = (const float*)d_in[13];
    const float* b4    = (const float*)d_in[14];
    const float* h     = (const float*)d_in[15];
    const float* noise = (const float*)d_in[16];

    __half *xh, *wh, *ah, *sh, *xrh, *g1h, *g2h, *x2h, *th;
    cudaGetSymbolAddress((void**)&xh,  g_xh);
    cudaGetSymbolAddress((void**)&wh,  g_wh);
    cudaGetSymbolAddress((void**)&ah,  g_ah);
    cudaGetSymbolAddress((void**)&sh,  g_sh);
    cudaGetSymbolAddress((void**)&xrh, g_xrh);
    cudaGetSymbolAddress((void**)&g1h, g_g1h);
    cudaGetSymbolAddress((void**)&g2h, g_g2h);
    cudaGetSymbolAddress((void**)&x2h, g_x2h);
    cudaGetSymbolAddress((void**)&th,  g_th);

    cudaFuncSetAttribute(gemm_h<1, __half>, cudaFuncAttributeMaxDynamicSharedMemorySize, SMEM3);
    cudaFuncSetAttribute(gemm_h<0, __half>, cudaFuncAttributeMaxDynamicSharedMemorySize, SMEM3);
    cudaFuncSetAttribute(gemm_h<2, __half>, cudaFuncAttributeMaxDynamicSharedMemorySize, SMEM3);
    cudaFuncSetAttribute(gemm_h<0, float>,  cudaFuncAttributeMaxDynamicSharedMemorySize, SMEM3);
    cudaFuncSetAttribute(gemm_h<1, float>,  cudaFuncAttributeMaxDynamicSharedMemorySize, SMEM3);

    // single fused fp32 -> fp16 conversion (1 launch instead of 7)
    ConvArgs ca;
    ca.src[0] = x;   ca.dst[0] = xh;            ca.n4[0] = BB * D_IN / 4;
    ca.src[1] = w1;  ca.dst[1] = wh + OFF_W1;   ca.n4[1] = H1 * D_IN / 4;
    ca.src[2] = w2;  ca.dst[2] = wh + OFF_W2;   ca.n4[2] = CH * H1 / 4;
    ca.src[3] = wr1; ca.dst[3] = wh + OFF_WR1;  ca.n4[3] = HR * CH / 4;
    ca.src[4] = wr2; ca.dst[4] = wh + OFF_WR2;  ca.n4[4] = HR * HR / 4;
    ca.src[5] = w3;  ca.dst[5] = wh + OFF_W3;   ca.n4[5] = H2 * CH / 4;
    ca.src[6] = w4;  ca.dst[6] = wh + OFF_W4;   ca.n4[6] = D_OUTN * H2 / 4;
    ca.src[7] = x;   ca.dst[7] = xh;            ca.n4[7] = 0;   // unused
    conv_all_kernel<<<1184, 256>>>(ca);

    // encoder
    gemm_h<1, __half><<<dim3(BB / BM, H1 / BN), 256, SMEM3>>>(
        xh, wh + OFF_W1, b1, ah, BB, H1, D_IN);
    gemm_h<0, __half><<<dim3(BB / BM, CH / BN), 256, SMEM3>>>(
        ah, wh + OFF_W2, b2, sh, BB, CH, H1);
    // channel + equalization
    channel_kernel<<<BB, 128>>>(sh, noise, h, xrh);
    // RTN
    gemm_h<2, __half><<<dim3(BB / BM, HR / BN), 256, SMEM3>>>(
        xrh, wh + OFF_WR1, br1, g1h, BB, HR, CH);
    gemm_h<2, __half><<<dim3(BB / BM, HR / BN), 256, SMEM3>>>(
        g1h, wh + OFF_WR2, br2, g2h, BB, HR, HR);
    rtn_tail<<<BB, 256>>>(g2h, wr3, br3, xrh, x2h);
    // decoder
    gemm_h<1, __half><<<dim3(BB / BM, H2 / BN), 256, SMEM3>>>(
        x2h, wh + OFF_W3, b3, th, BB, H2, CH);
    gemm_h<0, float><<<dim3(BB / BM, D_OUTN / BN), 256, SMEM3>>>(
        th, wh + OFF_W4, b4, (float*)d_out, BB, D_OUTN, H2);
}

// round 7
// speedup vs baseline: 4.7347x; 1.0121x over previous
#include <cuda_runtime.h>
#include <cuda_fp16.h>
#include <cstdint>
#include <math.h>

#define BB    8192
#define D_IN  512
#define H1    4096
#define CH    256
#define HR    1024
#define H2    4096
#define D_OUTN 512

// ---------------- scratch (device globals; no allocation allowed) ----------
__device__ __half g_xh [(size_t)BB * D_IN];
__device__ __half g_wh [(size_t)7602176];       // all weights, fp16
__device__ __half g_ah [(size_t)BB * H1];
__device__ __half g_sh [(size_t)BB * CH];
__device__ __half g_xrh[(size_t)BB * CH];
__device__ __half g_g1h[(size_t)BB * HR];
__device__ __half g_g2h[(size_t)BB * HR];
__device__ __half g_x2h[(size_t)BB * CH];
__device__ __half g_th [(size_t)BB * H2];

#define OFF_W1  0
#define OFF_W2  2097152
#define OFF_WR1 3145728
#define OFF_WR2 3407872
#define OFF_W3  4456448
#define OFF_W4  5505024

// ---------------- helpers ----------------------------------------------------
__device__ __forceinline__ uint32_t smem_u32(const void* p) {
    uint32_t a;
    asm("{ .reg .u64 t; cvta.to.shared.u64 t, %1; cvt.u32.u64 %0, t; }"
        : "=r"(a) : "l"(p));
    return a;
}

__device__ __forceinline__ void cp_async16(uint32_t dst, const void* src) {
    asm volatile("cp.async.cg.shared.global [%0], [%1], 16;"
        :: "r"(dst), "l"(src) : "memory");
}
__device__ __forceinline__ void cp_commit() {
    asm volatile("cp.async.commit_group;" ::: "memory");
}
template <int N>
__device__ __forceinline__ void cp_wait() {
    asm volatile("cp.async.wait_group %0;" :: "n"(N) : "memory");
}

__device__ __forceinline__ void ldsm4(uint32_t& r0, uint32_t& r1,
                                      uint32_t& r2, uint32_t& r3, uint32_t a) {
    asm volatile("ldmatrix.sync.aligned.m8n8.x4.shared.b16 {%0,%1,%2,%3}, [%4];"
        : "=r"(r0), "=r"(r1), "=r"(r2), "=r"(r3) : "r"(a));
}

__device__ __forceinline__ void mma_f16(float* d, const uint32_t* a,
                                        uint32_t b0, uint32_t b1) {
    asm volatile(
        "mma.sync.aligned.m16n8k16.row.col.f32.f16.f16.f32 "
        "{%0,%1,%2,%3}, {%4,%5,%6,%7}, {%8,%9}, {%0,%1,%2,%3};"
        : "+f"(d[0]), "+f"(d[1]), "+f"(d[2]), "+f"(d[3])
        : "r"(a[0]), "r"(a[1]), "r"(a[2]), "r"(a[3]), "r"(b0), "r"(b1));
}

// ---------------- single fused fp32 -> fp16 conversion pass ------------------
struct ConvArgs {
    const float* src[8];
    __half*      dst[8];
    int          n4[8];     // element count / 4
};

__global__ void conv_all_kernel(ConvArgs a) {
    const int stride = gridDim.x * blockDim.x;
    const int t0 = blockIdx.x * blockDim.x + threadIdx.x;
#pragma unroll
    for (int s = 0; s < 8; ++s) {
        const float4* sp = (const float4*)a.src[s];
        __half2* dp = (__half2*)a.dst[s];
        const int n = a.n4[s];
        for (int i = t0; i < n; i += stride) {
            float4 v = sp[i];
            dp[2 * i]     = __floats2half2_rn(v.x, v.y);
            dp[2 * i + 1] = __floats2half2_rn(v.z, v.w);
        }
    }
}

// =============== fp16 GEMM: 128x128x64, 3-stage, 2 CTAs/SM ===================
#define BM 128
#define BN 128
#define BK 64
#define ROWB 144                      // padded row bytes (72 halfs)
#define ATILE_B (128 * ROWB)          // 18432
#define STAGE_B (2 * ATILE_B)         // 36864 (A + B)
#define SMEM3   (3 * STAGE_B)         // 110592

template <int ACT, typename OutT>     // ACT: 0 none, 1 relu, 2 tanh
__global__ void __launch_bounds__(256, 2)
gemm_h(const __half* __restrict__ A, const __half* __restrict__ W,
       const float* __restrict__ bias, OutT* __restrict__ C,
       int M, int N, int K)
{
    extern __shared__ char smc[];
    const uint32_t sb = smem_u32(smc);
    const int tid  = threadIdx.x;
    const int wid  = tid >> 5, lane = tid & 31;
    const int g    = lane >> 2, c = lane & 3;
    const int wm   = wid & 3, wn = wid >> 2;      // warp grid 4(M) x 2(N)
    const int bm   = blockIdx.x * BM;
    const int bn   = blockIdx.y * BN;

    const int lrow = tid >> 1;
    const int lsel = tid & 1;
    const __half* Ag = A + (size_t)(bm + lrow) * K + lsel * 32;
    const __half* Bg = W + (size_t)(bn + lrow) * K + lsel * 32;
    const uint32_t stA = sb + (uint32_t)(lrow * ROWB + lsel * 64);
    const uint32_t stB = stA + ATILE_B;

    float acc[2][8][4];
#pragma unroll
    for (int mt = 0; mt < 2; mt++)
#pragma unroll
        for (int nt = 0; nt < 8; nt++)
#pragma unroll
            for (int r = 0; r < 4; r++) acc[mt][nt][r] = 0.0f;

    const int nk = K / BK;

    // prefetch stages 0,1
#pragma unroll
    for (int s = 0; s < 2; ++s) {
        const uint32_t base = s * STAGE_B;
        const int off = s * BK;
#pragma unroll
        for (int i = 0; i < 4; i++) {
            cp_async16(stA + base + i * 16, Ag + off + i * 8);
            cp_async16(stB + base + i * 16, Bg + off + i * 8);
        }
        cp_commit();
    }

    const uint32_t aBase = (uint32_t)((wm * 32 + (lane & 15)) * ROWB + (lane >> 4) * 16);
    const uint32_t bBase = (uint32_t)ATILE_B +
        (uint32_t)((wn * 64 + (lane & 7) + ((lane >> 4) << 3)) * ROWB +
                   ((lane >> 3) & 1) * 16);

    int stage = 0, nstage = 2;
    for (int it = 0; it < nk; ++it) {
        cp_wait<1>();
        __syncthreads();

        if (it + 2 < nk) {
            const uint32_t base = nstage * STAGE_B;
            const int off = (it + 2) * BK;
#pragma unroll
            for (int i = 0; i < 4; i++) {
                cp_async16(stA + base + i * 16, Ag + off + i * 8);
                cp_async16(stB + base + i * 16, Bg + off + i * 8);
            }
        }
        cp_commit();
        nstage = nstage + 1 == 3 ? 0 : nstage + 1;

        const uint32_t tb = sb + stage * STAGE_B;
        stage = stage + 1 == 3 ? 0 : stage + 1;

        // A-fragment double buffering across ks-steps
        uint32_t afr[2][2][4];
        ldsm4(afr[0][0][0], afr[0][0][1], afr[0][0][2], afr[0][0][3],
              tb + aBase);
        ldsm4(afr[0][1][0], afr[0][1][1], afr[0][1][2], afr[0][1][3],
              tb + aBase + 16 * ROWB);
#pragma unroll
        for (int ks = 0; ks < 4; ++ks) {
            const int cur = ks & 1, nxt = cur ^ 1;
            if (ks < 3) {
                ldsm4(afr[nxt][0][0], afr[nxt][0][1], afr[nxt][0][2], afr[nxt][0][3],
                      tb + aBase + (ks + 1) * 32);
                ldsm4(afr[nxt][1][0], afr[nxt][1][1], afr[nxt][1][2], afr[nxt][1][3],
                      tb + aBase + 16 * ROWB + (ks + 1) * 32);
            }
#pragma unroll
            for (int np = 0; np < 4; ++np) {
                uint32_t b0, b1, b2, b3;
                ldsm4(b0, b1, b2, b3, tb + bBase + np * 16 * ROWB + ks * 32);
                mma_f16(acc[0][2 * np],     afr[cur][0], b0, b1);
                mma_f16(acc[1][2 * np],     afr[cur][1], b0, b1);
                mma_f16(acc[0][2 * np + 1], afr[cur][0], b2, b3);
                mma_f16(acc[1][2 * np + 1], afr[cur][1], b2, b3);
            }
        }
    }

    // epilogue: bias + activation
#pragma unroll
    for (int nt = 0; nt < 8; ++nt) {
        const int colb = bn + wn * 64 + nt * 8 + 2 * c;
        const float bz0 = bias[colb], bz1 = bias[colb + 1];
#pragma unroll
        for (int mt = 0; mt < 2; ++mt) {
            const int row0 = bm + wm * 32 + mt * 16 + g;
            float o0 = acc[mt][nt][0] + bz0;
            float o1 = acc[mt][nt][1] + bz1;
            float o2 = acc[mt][nt][2] + bz0;
            float o3 = acc[mt][nt][3] + bz1;
            if (ACT == 1) {
                o0 = fmaxf(o0, 0.f); o1 = fmaxf(o1, 0.f);
                o2 = fmaxf(o2, 0.f); o3 = fmaxf(o3, 0.f);
            }
            if (ACT == 2) {
                o0 = tanhf(o0); o1 = tanhf(o1);
                o2 = tanhf(o2); o3 = tanhf(o3);
            }
            if (sizeof(OutT) == 2) {
                *(__half2*)((__half*)C + (size_t)row0 * N + colb) =
                    __floats2half2_rn(o0, o1);
                *(__half2*)((__half*)C + (size_t)(row0 + 8) * N + colb) =
                    __floats2half2_rn(o2, o3);
            } else {
                *(float2*)((float*)C + (size_t)row0 * N + colb) = make_float2(o0, o1);
                *(float2*)((float*)C + (size_t)(row0 + 8) * N + colb) = make_float2(o2, o3);
            }
        }
    }
}

// ---------------- per-row channel: warp-per-row, shuffle-only ----------------
// den = sum |tx|^2 == 128 exactly after power normalization, so only two
// reductions (sumsq, num) are needed and no smem/syncthreads at all.
__global__ void __launch_bounds__(256)
channel_kernel(const __half* __restrict__ s, const float* __restrict__ noise,
               const float* __restrict__ h, __half* __restrict__ xr)
{
    const int lane = threadIdx.x & 31;
    const int row  = blockIdx.x * 8 + (threadIdx.x >> 5);
    const __half2* sp = (const __half2*)(s + (size_t)row * CH);
    const float2*  np = (const float2*)(noise + (size_t)row * CH);

    float2 sv[4], nv[4];
    float sumsq = 0.f;
#pragma unroll
    for (int j = 0; j < 4; ++j) {
        sv[j] = __half22float2(sp[lane + 32 * j]);
        nv[j] = np[lane + 32 * j];
        sumsq += sv[j].x * sv[j].x + sv[j].y * sv[j].y;
    }
#pragma unroll
    for (int o = 16; o; o >>= 1) sumsq += __shfl_xor_sync(0xffffffffu, sumsq, o);
    const float scale = sqrtf(128.0f) * rsqrtf(sumsq);
    const float h0 = h[0], h1 = h[1];

    float yr[4], yi[4];
    float numr = 0.f, numi = 0.f;
#pragma unroll
    for (int j = 0; j < 4; ++j) {
        const float txr = scale * sv[j].x, txi = scale * sv[j].y;
        yr[j] = h0 * txr - h1 * txi + nv[j].x;
        yi[j] = h0 * txi + h1 * txr + nv[j].y;
        numr += yr[j] * txr + yi[j] * txi;
        numi += yi[j] * txr - yr[j] * txi;
    }
#pragma unroll
    for (int o = 16; o; o >>= 1) {
        numr += __shfl_xor_sync(0xffffffffu, numr, o);
        numi += __shfl_xor_sync(0xffffffffu, numi, o);
    }
    const float hr = numr * (1.0f / 128.0f);
    const float hi = numi * (1.0f / 128.0f);
    const float inv = 1.0f / (hr * hr + hi * hi + 1e-12f);
    __half2* op = (__half2*)(xr + (size_t)row * CH);
#pragma unroll
    for (int j = 0; j < 4; ++j) {
        const float xe_r = (yr[j] * hr + yi[j] * hi) * inv;
        const float xe_i = (yi[j] * hr - yr[j] * hi) * inv;
        op[lane + 32 * j] = __floats2half2_rn(xe_r, xe_i);
    }
}

// ---------------- RTN tail: h_inv = g2 @ w_rtn3^T + b; 3-tap complex conv --
__global__ void __launch_bounds__(256)
rtn_tail(const __half* __restrict__ g2, const float* __restrict__ w_rtn3,
         const float* __restrict__ b_rtn3, const __half* __restrict__ xr,
         __half* __restrict__ xr2)
{
    __shared__ float xs[CH];
    __shared__ float red[6][8];
    __shared__ float hinv[6];

    const int row = blockIdx.x, tid = threadIdx.x;
    for (int i = tid; i < CH; i += 256) xs[i] = __half2float(xr[(size_t)row * CH + i]);

    float acc[6] = {0, 0, 0, 0, 0, 0};
    for (int i = tid; i < HR; i += 256) {
        const float gv = __half2float(g2[(size_t)row * HR + i]);
#pragma unroll
        for (int o = 0; o < 6; o++) acc[o] += gv * w_rtn3[o * HR + i];
    }
#pragma unroll
    for (int o = 0; o < 6; o++) {
        float v = acc[o];
#pragma unroll
        for (int sft = 16; sft; sft >>= 1) v += __shfl_down_sync(0xffffffffu, v, sft);
        if ((tid & 31) == 0) red[o][tid >> 5] = v;
    }
    __syncthreads();
    if (tid < 6) {
        float v = 0;
#pragma unroll
        for (int w = 0; w < 8; w++) v += red[tid][w];
        hinv[tid] = v + b_rtn3[tid];
    }
    __syncthreads();

    if (tid < 128) {
        float or_ = 0.0f, oi_ = 0.0f;
#pragma unroll
        for (int l = 0; l < 3; l++) {
            if (tid - l >= 0) {
                const float hrr = hinv[2 * l], hii = hinv[2 * l + 1];
                const float xrr = xs[2 * (tid - l)], xii = xs[2 * (tid - l) + 1];
                or_ += hrr * xrr - hii * xii;
                oi_ += hrr * xii + hii * xrr;
            }
        }
        *(__half2*)(xr2 + (size_t)row * CH + 2 * tid) = __floats2half2_rn(or_, oi_);
    }
}

// ---------------- launcher --------------------------------------------------
extern "C" void kernel_launch(void* const* d_in, const int* in_sizes, int n_in,
                              void* d_out, int out_size)
{
    const float* x     = (const float*)d_in[0];
    const float* w1    = (const float*)d_in[1];
    const float* b1    = (const float*)d_in[2];
    const float* w2    = (const float*)d_in[3];
    const float* b2    = (const float*)d_in[4];
    const float* wr1   = (const float*)d_in[5];
    const float* br1   = (const float*)d_in[6];
    const float* wr2   = (const float*)d_in[7];
    const float* br2   = (const float*)d_in[8];
    const float* wr3   = (const float*)d_in[9];
    const float* br3   = (const float*)d_in[10];
    const float* w3    = (const float*)d_in[11];
    const float* b3    = (const float*)d_in[12];
    const float* w4    = (const float*)d_in[13];
    const float* b4    = (const float*)d_in[14];
    const float* h     = (const float*)d_in[15];
    const float* noise = (const float*)d_in[16];

    __half *xh, *wh, *ah, *sh, *xrh, *g1h, *g2h, *x2h, *th;
    cudaGetSymbolAddress((void**)&xh,  g_xh);
    cudaGetSymbolAddress((void**)&wh,  g_wh);
    cudaGetSymbolAddress((void**)&ah,  g_ah);
    cudaGetSymbolAddress((void**)&sh,  g_sh);
    cudaGetSymbolAddress((void**)&xrh, g_xrh);
    cudaGetSymbolAddress((void**)&g1h, g_g1h);
    cudaGetSymbolAddress((void**)&g2h, g_g2h);
    cudaGetSymbolAddress((void**)&x2h, g_x2h);
    cudaGetSymbolAddress((void**)&th,  g_th);

    cudaFuncSetAttribute(gemm_h<1, __half>, cudaFuncAttributeMaxDynamicSharedMemorySize, SMEM3);
    cudaFuncSetAttribute(gemm_h<0, __half>, cudaFuncAttributeMaxDynamicSharedMemorySize, SMEM3);
    cudaFuncSetAttribute(gemm_h<2, __half>, cudaFuncAttributeMaxDynamicSharedMemorySize, SMEM3);
    cudaFuncSetAttribute(gemm_h<0, float>,  cudaFuncAttributeMaxDynamicSharedMemorySize, SMEM3);

    // single fused fp32 -> fp16 conversion (1 launch)
    ConvArgs ca;
    ca.src[0] = x;   ca.dst[0] = xh;            ca.n4[0] = BB * D_IN / 4;
    ca.src[1] = w1;  ca.dst[1] = wh + OFF_W1;   ca.n4[1] = H1 * D_IN / 4;
    ca.src[2] = w2;  ca.dst[2] = wh + OFF_W2;   ca.n4[2] = CH * H1 / 4;
    ca.src[3] = wr1; ca.dst[3] = wh + OFF_WR1;  ca.n4[3] = HR * CH / 4;
    ca.src[4] = wr2; ca.dst[4] = wh + OFF_WR2;  ca.n4[4] = HR * HR / 4;
    ca.src[5] = w3;  ca.dst[5] = wh + OFF_W3;   ca.n4[5] = H2 * CH / 4;
    ca.src[6] = w4;  ca.dst[6] = wh + OFF_W4;   ca.n4[6] = D_OUTN * H2 / 4;
    ca.src[7] = x;   ca.dst[7] = xh;            ca.n4[7] = 0;   // unused
    conv_all_kernel<<<1184, 256>>>(ca);

    // encoder
    gemm_h<1, __half><<<dim3(BB / BM, H1 / BN), 256, SMEM3>>>(
        xh, wh + OFF_W1, b1, ah, BB, H1, D_IN);
    gemm_h<0, __half><<<dim3(BB / BM, CH / BN), 256, SMEM3>>>(
        ah, wh + OFF_W2, b2, sh, BB, CH, H1);
    // channel + equalization (warp-per-row)
    channel_kernel<<<BB / 8, 256>>>(sh, noise, h, xrh);
    // RTN
    gemm_h<2, __half><<<dim3(BB / BM, HR / BN), 256, SMEM3>>>(
        xrh, wh + OFF_WR1, br1, g1h, BB, HR, CH);
    gemm_h<2, __half><<<dim3(BB / BM, HR / BN), 256, SMEM3>>>(
        g1h, wh + OFF_WR2, br2, g2h, BB, HR, HR);
    rtn_tail<<<BB, 256>>>(g2h, wr3, br3, xrh, x2h);
    // decoder
    gemm_h<1, __half><<<dim3(BB / BM, H2 / BN), 256, SMEM3>>>(
        x2h, wh + OFF_W3, b3, th, BB, H2, CH);
    gemm_h<0, float><<<dim3(BB / BM, D_OUTN / BN), 256, SMEM3>>>(
        th, wh + OFF_W4, b4, (float*)d_out, BB, D_OUTN, H2);
}